// round 14
// baseline (speedup 1.0000x reference)
#include <cuda_runtime.h>
#include <cuda_bf16.h>
#include <math.h>

// ---------------- problem constants ----------------
#define TT   128
#define BB   32
#define NTB  4096            // T*B
#define HID  256
#define FEAT 512
#define FLAT 3136            // 64*7*7
#define KPAD 3200            // padded FC K (64 ch x 50)
#define NACT 6

// output layout: logits[4096*6], v[4096], h[32*256], c[32*256]
#define OUT_V    24576
#define OUT_H    28672
#define OUT_C    36864

// ---------------- packed f32x2 helpers (LSTM) ----------------
typedef unsigned long long u64t;
__device__ __forceinline__ u64t pk2(float lo, float hi) {
    u64t r;
    asm("mov.b64 %0, {%1, %2};" : "=l"(r) : "f"(lo), "f"(hi));
    return r;
}
__device__ __forceinline__ void fma2(u64t& d, u64t a, u64t b) {
    asm("fma.rn.f32x2 %0, %1, %2, %0;" : "+l"(d) : "l"(a), "l"(b));
}
__device__ __forceinline__ float2 upk2(u64t v) {
    float2 f;
    asm("mov.b64 {%0, %1}, %2;" : "=f"(f.x), "=f"(f.y) : "l"(v));
    return f;
}

// ---------------- bf16 helpers ----------------
__device__ __forceinline__ void mma_bf16(float c[4], const unsigned a[4],
                                         unsigned b0, unsigned b1) {
    asm volatile(
        "mma.sync.aligned.m16n8k16.row.col.f32.bf16.bf16.f32 "
        "{%0,%1,%2,%3}, {%4,%5,%6,%7}, {%8,%9}, {%0,%1,%2,%3};"
        : "+f"(c[0]), "+f"(c[1]), "+f"(c[2]), "+f"(c[3])
        : "r"(a[0]), "r"(a[1]), "r"(a[2]), "r"(a[3]), "r"(b0), "r"(b1));
}
__device__ __forceinline__ void bf_split(float x, __nv_bfloat16& h, __nv_bfloat16& l) {
    h = __float2bfloat16(x);
    l = __float2bfloat16(x - __bfloat162float(h));
}
__device__ __forceinline__ unsigned pack_bf2(__nv_bfloat16 a, __nv_bfloat16 b) {
    __nv_bfloat162 v(a, b);
    return *(unsigned*)&v;
}
__device__ __forceinline__ unsigned lo32(u64t v) { return (unsigned)v; }
__device__ __forceinline__ unsigned hi32(u64t v) { return (unsigned)(v >> 32); }
// split two fp32 into packed hi/lo words
__device__ __forceinline__ void split_pair(float x0, float x1,
                                           unsigned& wh, unsigned& wl) {
    __nv_bfloat16 h0, l0, h1, l1;
    bf_split(x0, h0, l0);
    bf_split(x1, h1, l1);
    wh = pack_bf2(h0, h1);
    wl = pack_bf2(l0, l1);
}

// ---------------- scratch ----------------
__device__ unsigned g_c1h[(size_t)NTB*32*200];      // conv1 out, packed [n][32][400/2]
__device__ unsigned g_c1l[(size_t)NTB*32*200];
__device__ unsigned g_c2h[(size_t)NTB*64*41];       // conv2 out, padded stride 82 -> 41 words
__device__ unsigned g_c2l[(size_t)NTB*64*41];
__device__ unsigned g_c3h[(size_t)NTB*1600];        // conv3 out, padded stride 50 -> 25 w/ch
__device__ unsigned g_c3l[(size_t)NTB*1600];
__device__ unsigned g_fwh[(size_t)FEAT*1600];       // fc_w packed, padded K=3200
__device__ unsigned g_fwl[(size_t)FEAT*1600];
__device__ unsigned g_fth[(size_t)NTB*FEAT/2];      // feats packed
__device__ unsigned g_ftl[(size_t)NTB*FEAT/2];
__device__ unsigned g_wih_h[(size_t)4*HID*FEAT/2];
__device__ unsigned g_wih_l[(size_t)4*HID*FEAT/2];
__device__ float g_gx[(size_t)NTB*4*HID];
__device__ float g_hs[(size_t)NTB*HID];
__device__ float g_h[BB*HID];
__device__ unsigned g_bar;
__device__ unsigned g_exit;

// ======================================================================
// weight pack kernels
// ======================================================================
__global__ void pack_split_kernel(const float* __restrict__ src,
                                  unsigned* __restrict__ dh,
                                  unsigned* __restrict__ dl,
                                  int nw) {
    for (int i = blockIdx.x * blockDim.x + threadIdx.x; i < nw;
         i += gridDim.x * blockDim.x) {
        float2 x = ((const float2*)src)[i];
        unsigned wh, wl;
        split_pair(x.x, x.y, wh, wl);
        dh[i] = wh; dl[i] = wl;
    }
}
// fc_w [512][3136] -> padded packed [512][1600 words], ch stride 50 (pad=0)
__global__ void pack_fcw_kernel(const float* __restrict__ w,
                                unsigned* __restrict__ dh,
                                unsigned* __restrict__ dl) {
    int nw = FEAT * 1600;
    for (int i = blockIdx.x * blockDim.x + threadIdx.x; i < nw;
         i += gridDim.x * blockDim.x) {
        int f = i / 1600, q = i % 1600;
        int e0 = 2 * q;
        int co = e0 / 50, p0 = e0 % 50;     // p0 even <= 48
        float x0 = w[(size_t)f * FLAT + co * 49 + p0];
        float x1 = (p0 + 1 < 49) ? w[(size_t)f * FLAT + co * 49 + p0 + 1] : 0.f;
        unsigned wh, wl;
        split_pair(x0, x1, wh, wl);
        dh[i] = wh; dl[i] = wl;
    }
}

// ======================================================================
// bf16x3 implicit-GEMM conv, hi/lo interleaved smem, PACKED output.
// INPK: input is packed hi/lo word buffers (else fp32 with optional scale).
// OPW: output words per channel (pads with zero when col+1 >= NPOS).
// ======================================================================
template<int CIN,int KW,int S,int IW,int OW,int MCH,int KC,int NG,int MAXNT,
         bool SCALE,bool INPK,int OPW>
__global__ void __launch_bounds__(256, 2)
conv_bf3_kernel(const float* __restrict__ src,
                const unsigned* __restrict__ srch,
                const unsigned* __restrict__ srcl,
                const float* __restrict__ w,
                const float* __restrict__ bias,
                unsigned* __restrict__ dsth,
                unsigned* __restrict__ dstl) {
    constexpr int K    = CIN * KW * KW;
    constexpr int NPOS = OW * OW;
    constexpr int ISZ  = CIN * IW * IW;
    constexpr int NCH  = K / KC;
    constexpr int WSW  = KC + 2;
    constexpr int NTT  = (NPOS + 7) / 8;
    constexpr int IPAIR = ISZ / 2;

    extern __shared__ unsigned smw[];
    unsigned* iw = smw;                         // (IPAIR+8)*2 words
    unsigned* ww = iw + (IPAIR + 8) * 2;        // MCH*WSW words
    int* kof = (int*)(ww + MCH * WSW);          // [K]

    int n = blockIdx.x, t = threadIdx.x;

    if (INPK) {
        const unsigned* sh = srch + (size_t)n * IPAIR;
        const unsigned* sl = srcl + (size_t)n * IPAIR;
        for (int i = t; i < IPAIR; i += 256) {
            iw[2 * i]     = sh[i];
            iw[2 * i + 1] = sl[i];
        }
    } else {
        const float* s = src + (size_t)n * ISZ;
        for (int i = t; i < IPAIR; i += 256) {
            float x0 = s[2 * i], x1 = s[2 * i + 1];
            if (SCALE) { x0 *= (1.0f / 255.0f); x1 *= (1.0f / 255.0f); }
            unsigned wh, wl;
            split_pair(x0, x1, wh, wl);
            iw[2 * i]     = wh;
            iw[2 * i + 1] = wl;
        }
    }
    if (t < 16) iw[IPAIR * 2 + t] = 0u;
    for (int i = t; i < K; i += 256) {
        int c = i / (KW * KW), r = i % (KW * KW);
        kof[i] = (c * IW + r / KW) * IW + (r % KW);
    }

    int wid = t >> 5, lane = t & 31;
    int gid = lane >> 2, tid4 = lane & 3;
    int wm, ng;
    if (MCH == 32) { wm = wid >> 2; ng = wid & 3; }
    else           { wm = wid >> 1; ng = wid & 1; }
    int m0 = wm * 16 + gid;

    int nbase[MAXNT];
    bool nval[MAXNT];
#pragma unroll
    for (int j = 0; j < MAXNT; j++) {
        int nt = ng + j * NG;
        int p = nt * 8 + gid;
        bool v = (nt < NTT) && (p < NPOS);
        nval[j] = v;
        int oy = p / OW, ox = p % OW;
        nbase[j] = v ? (oy * S * IW + ox * S) : 0;
    }

    float acc[MAXNT][4];
#pragma unroll
    for (int j = 0; j < MAXNT; j++)
        acc[j][0] = acc[j][1] = acc[j][2] = acc[j][3] = 0.f;

    for (int ck = 0; ck < NCH; ck++) {
        __syncthreads();
        for (int i = t; i < MCH * (KC / 2); i += 256) {
            int m = i / (KC / 2), q = i % (KC / 2);
            float x0 = w[(size_t)m * K + ck * KC + 2 * q];
            float x1 = w[(size_t)m * K + ck * KC + 2 * q + 1];
            unsigned wh, wl;
            split_pair(x0, x1, wh, wl);
            ww[m * WSW + 2 * q]     = wh;
            ww[m * WSW + 2 * q + 1] = wl;
        }
        __syncthreads();

        for (int k16 = 0; k16 < KC / 16; k16++) {
            int wq = k16 * 8 + tid4;
            u64t A0 = *(const u64t*)&ww[m0 * WSW + 2 * wq];
            u64t A1 = *(const u64t*)&ww[(m0 + 8) * WSW + 2 * wq];
            u64t A2 = *(const u64t*)&ww[m0 * WSW + 2 * wq + 8];
            u64t A3 = *(const u64t*)&ww[(m0 + 8) * WSW + 2 * wq + 8];
            unsigned ah[4] = {lo32(A0), lo32(A1), lo32(A2), lo32(A3)};
            unsigned al[4] = {hi32(A0), hi32(A1), hi32(A2), hi32(A3)};

            int kbase = ck * KC + k16 * 16;
            int oa = kof[kbase + 2 * tid4];
            int ob = kof[kbase + 8 + 2 * tid4];
#pragma unroll
            for (int j = 0; j < MAXNT; j += 2) {
                unsigned p0h, p1h, p0l, p1l;
                unsigned q0h, q1h, q0l, q1l;
                if (nval[j]) {
                    u64t B0 = *(const u64t*)&iw[(oa + nbase[j])];
                    u64t B1 = *(const u64t*)&iw[(ob + nbase[j])];
                    p0h = lo32(B0); p0l = hi32(B0);
                    p1h = lo32(B1); p1l = hi32(B1);
                } else { p0h = p1h = p0l = p1l = 0u; }
                if (j + 1 < MAXNT) {
                    if (nval[j + 1]) {
                        u64t B0 = *(const u64t*)&iw[(oa + nbase[j + 1])];
                        u64t B1 = *(const u64t*)&iw[(ob + nbase[j + 1])];
                        q0h = lo32(B0); q0l = hi32(B0);
                        q1h = lo32(B1); q1l = hi32(B1);
                    } else { q0h = q1h = q0l = q1l = 0u; }
                }
                mma_bf16(acc[j], ah, p0h, p1h);
                if (j + 1 < MAXNT) mma_bf16(acc[j + 1], ah, q0h, q1h);
                mma_bf16(acc[j], ah, p0l, p1l);
                if (j + 1 < MAXNT) mma_bf16(acc[j + 1], ah, q0l, q1l);
                mma_bf16(acc[j], al, p0h, p1h);
                if (j + 1 < MAXNT) mma_bf16(acc[j + 1], al, q0h, q1h);
            }
        }
    }

    // packed epilogue: relu, split, write hi/lo words (pad second elem = 0)
    unsigned* bh = dsth + (size_t)n * MCH * OPW;
    unsigned* bl = dstl + (size_t)n * MCH * OPW;
    float b0 = __ldg(&bias[m0]);
    float b1 = __ldg(&bias[m0 + 8]);
#pragma unroll
    for (int j = 0; j < MAXNT; j++) {
        int nt = ng + j * NG;
        if (nt >= NTT) continue;
        int col = nt * 8 + tid4 * 2;
        if (col < NPOS) {
            bool has2 = (col + 1 < NPOS);
            float r0 = fmaxf(acc[j][0] + b0, 0.f);
            float r1 = has2 ? fmaxf(acc[j][1] + b0, 0.f) : 0.f;
            float r2 = fmaxf(acc[j][2] + b1, 0.f);
            float r3 = has2 ? fmaxf(acc[j][3] + b1, 0.f) : 0.f;
            unsigned wh, wl;
            split_pair(r0, r1, wh, wl);
            bh[m0 * OPW + (col >> 1)] = wh;
            bl[m0 * OPW + (col >> 1)] = wl;
            split_pair(r2, r3, wh, wl);
            bh[(m0 + 8) * OPW + (col >> 1)] = wh;
            bl[(m0 + 8) * OPW + (col >> 1)] = wl;
        }
    }
}

// conv1: KC=192 single chunk, out [32][200w].  conv2: KC=128, out padded [64][41w].
#define C1B_SMEM (((21168/2 + 8) * 2 + 32 * 194) * 4 + 192 * 4)
#define C2B_SMEM (((12800/2 + 8) * 2 + 64 * 130) * 4 + 512 * 4)

// ======================================================================
// conv3 bf16x3 MMA: packed padded input (plane stride 82), dual planes via
// funnel-shift; packed padded output (ch stride 50).
// ======================================================================
#define C3M_IPAIR 2624                      // 64*41 input word-pairs
#define C3M_IWRDS ((C3M_IPAIR + 8) * 2)
#define C3M_WSW   194
#define C3M_SMEM  ((2 * C3M_IWRDS + 64 * C3M_WSW) * 4 + 768 * 4)
__global__ void __launch_bounds__(256, 2)
conv3_mma_kernel(const unsigned* __restrict__ srch,
                 const unsigned* __restrict__ srcl,
                 const float* __restrict__ w,
                 const float* __restrict__ bias,
                 unsigned* __restrict__ dsth,
                 unsigned* __restrict__ dstl) {
    constexpr int IW = 9, OW = 7, NPOS = 49, MCH = 64;
    constexpr int K = 768, KC = 192, NCH = 4;
    constexpr int NTT = 7, NG = 2, MAXNT = 4, OPW = 25;

    extern __shared__ unsigned smw[];
    unsigned* iw = smw;
    unsigned* jw = iw + C3M_IWRDS;
    unsigned* ww = jw + C3M_IWRDS;
    int* kof = (int*)(ww + 64 * C3M_WSW);

    int n = blockIdx.x, t = threadIdx.x;
    const unsigned* sh = srch + (size_t)n * C3M_IPAIR;
    const unsigned* sl = srcl + (size_t)n * C3M_IPAIR;

    for (int p = t; p < C3M_IPAIR; p += 256) {
        iw[2 * p]     = sh[p];
        iw[2 * p + 1] = sl[p];
    }
    if (t < 16) iw[C3M_IPAIR * 2 + t] = 0u;
    for (int i = t; i < K; i += 256) {
        int kx = i & 3, ky = (i >> 2) % 3, c = i / 12;
        kof[i] = c * 82 + ky * 9 + kx;       // padded plane stride 82
    }
    __syncthreads();
    // shifted plane from iw words
    for (int p = t; p < C3M_IPAIR; p += 256) {
        jw[2 * p]     = __funnelshift_r(iw[2 * p],     iw[2 * p + 2], 16);
        jw[2 * p + 1] = __funnelshift_r(iw[2 * p + 1], iw[2 * p + 3], 16);
    }
    if (t < 16) jw[C3M_IPAIR * 2 + t] = 0u;

    int wid = t >> 5, lane = t & 31;
    int gid = lane >> 2, tid4 = lane & 3;
    int wm = wid >> 1, ng = wid & 1;
    int m0 = wm * 16 + gid;

    int nbase[MAXNT];
    bool nval[MAXNT];
#pragma unroll
    for (int j = 0; j < MAXNT; j++) {
        int nt = ng + j * NG;
        int p = nt * 8 + gid;
        bool v = (nt < NTT) && (p < NPOS);
        nval[j] = v;
        int oy = p / OW, ox = p % OW;
        nbase[j] = v ? (oy * IW + ox) : 0;
    }

    float acc[MAXNT][4];
#pragma unroll
    for (int j = 0; j < MAXNT; j++)
        acc[j][0] = acc[j][1] = acc[j][2] = acc[j][3] = 0.f;

    for (int ck = 0; ck < NCH; ck++) {
        __syncthreads();
        for (int i = t; i < MCH * (KC / 2); i += 256) {
            int m = i / (KC / 2), q = i % (KC / 2);
            int k = ck * KC + 2 * q;
            int kx = k & 3, ky = (k >> 2) % 3, c = k / 12;
            float x0 = w[((size_t)(m * 64 + c) * 3 + ky) * 3 + kx];
            float x1 = (kx == 0) ? w[((size_t)(m * 64 + c) * 3 + ky) * 3 + 1] : 0.f;
            unsigned wh, wl;
            split_pair(x0, x1, wh, wl);
            ww[m * C3M_WSW + 2 * q]     = wh;
            ww[m * C3M_WSW + 2 * q + 1] = wl;
        }
        __syncthreads();

        for (int k16 = 0; k16 < KC / 16; k16++) {
            int wq = k16 * 8 + tid4;
            u64t A0 = *(const u64t*)&ww[m0 * C3M_WSW + 2 * wq];
            u64t A1 = *(const u64t*)&ww[(m0 + 8) * C3M_WSW + 2 * wq];
            u64t A2 = *(const u64t*)&ww[m0 * C3M_WSW + 2 * wq + 8];
            u64t A3 = *(const u64t*)&ww[(m0 + 8) * C3M_WSW + 2 * wq + 8];
            unsigned ah[4] = {lo32(A0), lo32(A1), lo32(A2), lo32(A3)};
            unsigned al[4] = {hi32(A0), hi32(A1), hi32(A2), hi32(A3)};

            int kbase = ck * KC + k16 * 16;
            int oa = kof[kbase + 2 * tid4];
            int ob = kof[kbase + 8 + 2 * tid4];
#pragma unroll
            for (int j = 0; j < MAXNT; j += 2) {
                unsigned p0h, p1h, p0l, p1l, q0h, q1h, q0l, q1l;
                if (nval[j]) {
                    int e0 = oa + nbase[j];
                    int e1 = ob + nbase[j];
                    const unsigned* pp0 = (e0 & 1) ? (jw + e0 - 1) : (iw + e0);
                    const unsigned* pp1 = (e1 & 1) ? (jw + e1 - 1) : (iw + e1);
                    u64t B0 = *(const u64t*)pp0;
                    u64t B1 = *(const u64t*)pp1;
                    p0h = lo32(B0); p0l = hi32(B0);
                    p1h = lo32(B1); p1l = hi32(B1);
                } else { p0h = p1h = p0l = p1l = 0u; }
                if (nval[j + 1]) {
                    int e0 = oa + nbase[j + 1];
                    int e1 = ob + nbase[j + 1];
                    const unsigned* pp0 = (e0 & 1) ? (jw + e0 - 1) : (iw + e0);
                    const unsigned* pp1 = (e1 & 1) ? (jw + e1 - 1) : (iw + e1);
                    u64t B0 = *(const u64t*)pp0;
                    u64t B1 = *(const u64t*)pp1;
                    q0h = lo32(B0); q0l = hi32(B0);
                    q1h = lo32(B1); q1l = hi32(B1);
                } else { q0h = q1h = q0l = q1l = 0u; }
                mma_bf16(acc[j],     ah, p0h, p1h);
                mma_bf16(acc[j + 1], ah, q0h, q1h);
                mma_bf16(acc[j],     ah, p0l, p1l);
                mma_bf16(acc[j + 1], ah, q0l, q1l);
                mma_bf16(acc[j],     al, p0h, p1h);
                mma_bf16(acc[j + 1], al, q0h, q1h);
            }
        }
    }

    unsigned* bh = dsth + (size_t)n * MCH * OPW;
    unsigned* bl = dstl + (size_t)n * MCH * OPW;
    float b0 = __ldg(&bias[m0]);
    float b1 = __ldg(&bias[m0 + 8]);
#pragma unroll
    for (int j = 0; j < MAXNT; j++) {
        int nt = ng + j * NG;
        if (nt >= NTT) continue;
        int col = nt * 8 + tid4 * 2;
        if (col < NPOS) {
            bool has2 = (col + 1 < NPOS);
            float r0 = fmaxf(acc[j][0] + b0, 0.f);
            float r1 = has2 ? fmaxf(acc[j][1] + b0, 0.f) : 0.f;
            float r2 = fmaxf(acc[j][2] + b1, 0.f);
            float r3 = has2 ? fmaxf(acc[j][3] + b1, 0.f) : 0.f;
            unsigned wh, wl;
            split_pair(r0, r1, wh, wl);
            bh[m0 * OPW + (col >> 1)] = wh;
            bl[m0 * OPW + (col >> 1)] = wl;
            split_pair(r2, r3, wh, wl);
            bh[(m0 + 8) * OPW + (col >> 1)] = wh;
            bl[(m0 + 8) * OPW + (col >> 1)] = wl;
        }
    }
}

// ======================================================================
// bf16x3 GEMM, prepacked operands; optional PACKED output (fused split).
// ======================================================================
#define GEMM_SMEM 49152
template <bool RELU, bool PACKOUT>
__global__ void __launch_bounds__(256)
gemm_bf3p_kernel(const unsigned* __restrict__ Ahg, const unsigned* __restrict__ Alg,
                 const unsigned* __restrict__ Bhg, const unsigned* __restrict__ Blg,
                 const float* __restrict__ bias1,
                 const float* __restrict__ bias2,
                 float* __restrict__ C,
                 unsigned* __restrict__ Dh, unsigned* __restrict__ Dl,
                 int M, int N, int K) {
    extern __shared__ __nv_bfloat16 gsm[];
    __nv_bfloat16* Ah = gsm;            // [2][128][24]
    __nv_bfloat16* Al = gsm + 6144;
    __nv_bfloat16* Bh = gsm + 12288;
    __nv_bfloat16* Bl = gsm + 18432;

    int bm = blockIdx.y * 128, bn = blockIdx.x * 128;
    int t = threadIdx.x;
    int wid = t >> 5, lane = t & 31;
    int gid = lane >> 2, tid4 = lane & 3;
    int wm = (wid >> 1) * 32;
    int wn = (wid & 1) * 64;
    int lr = t >> 1, lc = (t & 1) * 8;
    int Kw = K >> 1;

    float c[2][8][4];
#pragma unroll
    for (int mt = 0; mt < 2; mt++)
#pragma unroll
        for (int nt = 0; nt < 8; nt++)
#pragma unroll
            for (int q = 0; q < 4; q++) c[mt][nt][q] = 0.f;

    const unsigned* ApH = Ahg + (size_t)(bm + lr) * Kw + (lc >> 1);
    const unsigned* ApL = Alg + (size_t)(bm + lr) * Kw + (lc >> 1);
    const unsigned* BpH = Bhg + (size_t)(bn + lr) * Kw + (lc >> 1);
    const unsigned* BpL = Blg + (size_t)(bn + lr) * Kw + (lc >> 1);

    {
        *(uint4*)(Ah + lr * 24 + lc) = *(const uint4*)(ApH);
        *(uint4*)(Al + lr * 24 + lc) = *(const uint4*)(ApL);
        *(uint4*)(Bh + lr * 24 + lc) = *(const uint4*)(BpH);
        *(uint4*)(Bl + lr * 24 + lc) = *(const uint4*)(BpL);
    }
    __syncthreads();

    int cur = 0;
    for (int k0 = 0; k0 < K; k0 += 16) {
        bool more = (k0 + 16) < K;
        uint4 a_h, a_l, b_h, b_l;
        if (more) {
            int wo = (k0 + 16) >> 1;
            a_h = *(const uint4*)(ApH + wo);
            a_l = *(const uint4*)(ApL + wo);
            b_h = *(const uint4*)(BpH + wo);
            b_l = *(const uint4*)(BpL + wo);
        }
        const unsigned* ahw = (const unsigned*)(Ah + cur * 3072);
        const unsigned* alw = (const unsigned*)(Al + cur * 3072);
        const unsigned* bhw = (const unsigned*)(Bh + cur * 3072);
        const unsigned* blw = (const unsigned*)(Bl + cur * 3072);
        unsigned afh[2][4], afl[2][4];
#pragma unroll
        for (int mt = 0; mt < 2; mt++) {
            int m = wm + mt * 16 + gid;
            afh[mt][0] = ahw[m * 12 + tid4];
            afh[mt][1] = ahw[(m + 8) * 12 + tid4];
            afh[mt][2] = ahw[m * 12 + tid4 + 4];
            afh[mt][3] = ahw[(m + 8) * 12 + tid4 + 4];
            afl[mt][0] = alw[m * 12 + tid4];
            afl[mt][1] = alw[(m + 8) * 12 + tid4];
            afl[mt][2] = alw[m * 12 + tid4 + 4];
            afl[mt][3] = alw[(m + 8) * 12 + tid4 + 4];
        }
        unsigned bfh[8][2], bfl[8][2];
#pragma unroll
        for (int nt = 0; nt < 8; nt++) {
            int nn = wn + nt * 8 + gid;
            bfh[nt][0] = bhw[nn * 12 + tid4];
            bfh[nt][1] = bhw[nn * 12 + tid4 + 4];
            bfl[nt][0] = blw[nn * 12 + tid4];
            bfl[nt][1] = blw[nn * 12 + tid4 + 4];
        }
#pragma unroll
        for (int mt = 0; mt < 2; mt++)
#pragma unroll
            for (int nt = 0; nt < 8; nt++)
                mma_bf16(c[mt][nt], afh[mt], bfh[nt][0], bfh[nt][1]);
#pragma unroll
        for (int mt = 0; mt < 2; mt++)
#pragma unroll
            for (int nt = 0; nt < 8; nt++)
                mma_bf16(c[mt][nt], afh[mt], bfl[nt][0], bfl[nt][1]);
#pragma unroll
        for (int mt = 0; mt < 2; mt++)
#pragma unroll
            for (int nt = 0; nt < 8; nt++)
                mma_bf16(c[mt][nt], afl[mt], bfh[nt][0], bfh[nt][1]);
        if (more) {
            int nxt = cur ^ 1;
            *(uint4*)(Ah + nxt * 3072 + lr * 24 + lc) = a_h;
            *(uint4*)(Al + nxt * 3072 + lr * 24 + lc) = a_l;
            *(uint4*)(Bh + nxt * 3072 + lr * 24 + lc) = b_h;
            *(uint4*)(Bl + nxt * 3072 + lr * 24 + lc) = b_l;
            __syncthreads();
            cur = nxt;
        }
    }

#pragma unroll
    for (int mt = 0; mt < 2; mt++) {
        int row = bm + wm + mt * 16 + gid;
#pragma unroll
        for (int nt = 0; nt < 8; nt++) {
            int col = bn + wn + nt * 8 + tid4 * 2;
            float bv0 = bias1[col], bv1 = bias1[col + 1];
            if (bias2) { bv0 += bias2[col]; bv1 += bias2[col + 1]; }
            float r0 = c[mt][nt][0] + bv0;
            float r1 = c[mt][nt][1] + bv1;
            float r2 = c[mt][nt][2] + bv0;
            float r3 = c[mt][nt][3] + bv1;
            if (RELU) {
                r0 = fmaxf(r0, 0.f); r1 = fmaxf(r1, 0.f);
                r2 = fmaxf(r2, 0.f); r3 = fmaxf(r3, 0.f);
            }
            if (PACKOUT) {
                unsigned wh, wl;
                split_pair(r0, r1, wh, wl);
                Dh[(size_t)row * (N >> 1) + (col >> 1)] = wh;
                Dl[(size_t)row * (N >> 1) + (col >> 1)] = wl;
                split_pair(r2, r3, wh, wl);
                Dh[(size_t)(row + 8) * (N >> 1) + (col >> 1)] = wh;
                Dl[(size_t)(row + 8) * (N >> 1) + (col >> 1)] = wl;
            } else {
                *(float2*)&C[(size_t)row * N + col]       = make_float2(r0, r1);
                *(float2*)&C[(size_t)(row + 8) * N + col] = make_float2(r2, r3);
            }
        }
    }
}

// ======================================================================
// persistent LSTM: 128 CTAs, each owns 2 hidden units.  (proven)
// ======================================================================
#define NBLK 128
#define LSTM_SMEM ((2048 + 8224 + 64 + 576) * 4)
__device__ __forceinline__ float sigmoidf(float x) { return 1.f / (1.f + expf(-x)); }

__global__ void __launch_bounds__(256)
lstm_kernel(const float* __restrict__ done,
            const float* __restrict__ h0,
            const float* __restrict__ c0,
            const float* __restrict__ whh,
            float* __restrict__ out) {
    extern __shared__ float sm[];
    float* w_s = sm;             // [k=256][r=8]
    float* h_s = sm + 2048;      // [32][257]
    float* c_s = h_s + 8224;     // [64]
    float* p_s = c_s + 64;       // [2][32][9]
    int t = threadIdx.x, blk = blockIdx.x;
    int j0 = blk * 2;

    for (int i = t; i < 2048; i += 256) {
        int k = i >> 3, r = i & 7;
        int q = r >> 1, jj = r & 1;
        w_s[i] = whh[(size_t)(q * HID + j0 + jj) * HID + k];
    }
    if (t < 64) {
        int b = t >> 1, jj = t & 1;
        c_s[t] = c0[b * HID + j0 + jj];
    }
    __syncthreads();

    int u = t & 127, half = t >> 7;
    int gb = u & 31, rq = u >> 5;
    unsigned target = 0;

    for (int step = 0; step < TT; step++) {
        float2 acc0;
        if (half == 0)
            acc0 = *(const float2*)&g_gx[(size_t)(step * BB + gb) * 4 * HID + rq * HID + j0];
        else
            acc0 = make_float2(0.f, 0.f);
        u64t accp = pk2(acc0.x, acc0.y);

        const float* hsrc = (step == 0) ? h0 : g_h;
        for (int i = t; i < BB * HID; i += 256) {
            int b = i >> 8;
            h_s[b * 257 + (i & 255)] = hsrc[i] * (1.0f - __ldg(&done[step * BB + b]));
        }
        __syncthreads();

        {
            const float* hp = &h_s[gb * 257 + half * 128];
            const float* wp = &w_s[(half * 128) * 8 + rq * 2];
#pragma unroll 8
            for (int k = 0; k < 128; k++) {
                float hv = hp[k];
                u64t hh = pk2(hv, hv);
                u64t wv = *(const u64t*)&wp[k * 8];
                fma2(accp, hh, wv);
            }
            float2 r = upk2(accp);
            float* pp = &p_s[half * 288 + gb * 9 + rq * 2];
            pp[0] = r.x; pp[1] = r.y;
        }
        __syncthreads();

        if (t < 64) {
            int b = t >> 1, jj = t & 1;
            float m = 1.0f - __ldg(&done[step * BB + b]);
            const float* p0 = &p_s[b * 9];
            const float* p1 = &p_s[288 + b * 9];
            float gi = p0[0 + jj] + p1[0 + jj];
            float gf = p0[2 + jj] + p1[2 + jj];
            float gg = p0[4 + jj] + p1[4 + jj];
            float go = p0[6 + jj] + p1[6 + jj];
            float I = sigmoidf(gi);
            float F = sigmoidf(gf);
            float G = tanhf(gg);
            float O = sigmoidf(go);
            float c_new = F * (m * c_s[t]) + I * G;
            c_s[t] = c_new;
            float h_new = O * tanhf(c_new);
            g_h[b * HID + j0 + jj] = h_new;
            g_hs[(size_t)(step * BB + b) * HID + j0 + jj] = h_new;
            if (step == TT - 1) {
                out[OUT_H + b * HID + j0 + jj] = h_new;
                out[OUT_C + b * HID + j0 + jj] = c_new;
            }
        }
        __threadfence();
        __syncthreads();
        if (t == 0) {
            atomicAdd(&g_bar, 1u);
            target += NBLK;
            while (*(volatile unsigned*)&g_bar < target) { }
        }
        __syncthreads();
    }

    if (t == 0) {
        unsigned v = atomicAdd(&g_exit, 1u);
        if (v == NBLK - 1) {
            atomicExch(&g_exit, 0u);
            atomicExch(&g_bar, 0u);
            __threadfence();
        }
    }
}

// ======================================================================
// heads
// ======================================================================
__global__ void heads_kernel(const float* __restrict__ pw,
                             const float* __restrict__ pb,
                             const float* __restrict__ vw,
                             const float* __restrict__ vb,
                             float* __restrict__ out) {
    __shared__ float ws[7 * 256];
    int t = threadIdx.x;
    for (int i = t; i < 6 * 256; i += 256) ws[i] = pw[i];
    if (t < 256) ws[1536 + t] = vw[t];
    __syncthreads();

    int warp = t >> 5, lane = t & 31;
    int row = blockIdx.x * 8 + warp;
    const float* hrow = g_hs + (size_t)row * 256;
    float p[7];
#pragma unroll
    for (int a = 0; a < 7; a++) p[a] = 0.f;
    for (int k = lane; k < 256; k += 32) {
        float hv = hrow[k];
#pragma unroll
        for (int a = 0; a < 7; a++) p[a] += hv * ws[a * 256 + k];
    }
#pragma unroll
    for (int a = 0; a < 7; a++)
#pragma unroll
        for (int off = 16; off; off >>= 1)
            p[a] += __shfl_xor_sync(0xffffffffu, p[a], off);
    if (lane == 0) {
#pragma unroll
        for (int a = 0; a < 6; a++) out[(size_t)row * 6 + a] = p[a] + pb[a];
        out[OUT_V + row] = p[6] + vb[0];
    }
}

// ======================================================================
// launch
// ======================================================================
extern "C" void kernel_launch(void* const* d_in, const int* in_sizes, int n_in,
                              void* d_out, int out_size) {
    const float* image = (const float*)d_in[0];
    const float* done  = (const float*)d_in[1];
    const float* h0    = (const float*)d_in[2];
    const float* c0    = (const float*)d_in[3];
    const float* c1w   = (const float*)d_in[4];
    const float* c1b   = (const float*)d_in[5];
    const float* c2w   = (const float*)d_in[6];
    const float* c2b   = (const float*)d_in[7];
    const float* c3w   = (const float*)d_in[8];
    const float* c3b   = (const float*)d_in[9];
    const float* fcw   = (const float*)d_in[10];
    const float* fcb   = (const float*)d_in[11];
    const float* wih   = (const float*)d_in[12];
    const float* whh   = (const float*)d_in[13];
    const float* bih   = (const float*)d_in[14];
    const float* bhh   = (const float*)d_in[15];
    const float* polw  = (const float*)d_in[16];
    const float* polb  = (const float*)d_in[17];
    const float* valw  = (const float*)d_in[18];
    const float* valb  = (const float*)d_in[19];
    float* out = (float*)d_out;

    auto conv1 = conv_bf3_kernel<3, 8, 4, 84, 20, 32, 192, 4, 13, true, false, 200>;
    auto conv2 = conv_bf3_kernel<32, 4, 2, 20, 9, 64, 128, 2, 6, false, true, 41>;

    cudaFuncSetAttribute(conv1, cudaFuncAttributeMaxDynamicSharedMemorySize, C1B_SMEM);
    cudaFuncSetAttribute(conv2, cudaFuncAttributeMaxDynamicSharedMemorySize, C2B_SMEM);
    cudaFuncSetAttribute(conv3_mma_kernel, cudaFuncAttributeMaxDynamicSharedMemorySize, C3M_SMEM);
    cudaFuncSetAttribute(gemm_bf3p_kernel<true, true>,   cudaFuncAttributeMaxDynamicSharedMemorySize, GEMM_SMEM);
    cudaFuncSetAttribute(gemm_bf3p_kernel<false, false>, cudaFuncAttributeMaxDynamicSharedMemorySize, GEMM_SMEM);
    cudaFuncSetAttribute(lstm_kernel, cudaFuncAttributeMaxDynamicSharedMemorySize, LSTM_SMEM);

    void *p_c1h, *p_c1l, *p_c2h, *p_c2l, *p_c3h, *p_c3l;
    void *p_fwh, *p_fwl, *p_fth, *p_ftl, *p_wih_h, *p_wih_l, *p_gx;
    cudaGetSymbolAddress(&p_c1h, g_c1h);  cudaGetSymbolAddress(&p_c1l, g_c1l);
    cudaGetSymbolAddress(&p_c2h, g_c2h);  cudaGetSymbolAddress(&p_c2l, g_c2l);
    cudaGetSymbolAddress(&p_c3h, g_c3h);  cudaGetSymbolAddress(&p_c3l, g_c3l);
    cudaGetSymbolAddress(&p_fwh, g_fwh);  cudaGetSymbolAddress(&p_fwl, g_fwl);
    cudaGetSymbolAddress(&p_fth, g_fth);  cudaGetSymbolAddress(&p_ftl, g_ftl);
    cudaGetSymbolAddress(&p_wih_h, g_wih_h);  cudaGetSymbolAddress(&p_wih_l, g_wih_l);
    cudaGetSymbolAddress(&p_gx, g_gx);

    // weight packs (cheap, run first)
    pack_fcw_kernel<<<592, 256>>>(fcw, (unsigned*)p_fwh, (unsigned*)p_fwl);
    pack_split_kernel<<<592, 256>>>(wih, (unsigned*)p_wih_h, (unsigned*)p_wih_l,
                                    4 * HID * FEAT / 2);

    conv1<<<NTB, 256, C1B_SMEM>>>(image, nullptr, nullptr, c1w, c1b,
                                  (unsigned*)p_c1h, (unsigned*)p_c1l);
    conv2<<<NTB, 256, C2B_SMEM>>>(nullptr, (const unsigned*)p_c1h,
                                  (const unsigned*)p_c1l, c2w, c2b,
                                  (unsigned*)p_c2h, (unsigned*)p_c2l);
    conv3_mma_kernel<<<NTB, 256, C3M_SMEM>>>((const unsigned*)p_c2h,
                                             (const unsigned*)p_c2l, c3w, c3b,
                                             (unsigned*)p_c3h, (unsigned*)p_c3l);

    // feats = relu(flat @ fc_w^T + fc_b), K padded to 3200; packed output
    gemm_bf3p_kernel<true, true><<<dim3(FEAT / 128, NTB / 128), 256, GEMM_SMEM>>>(
        (const unsigned*)p_c3h, (const unsigned*)p_c3l,
        (const unsigned*)p_fwh, (const unsigned*)p_fwl,
        fcb, nullptr, nullptr, (unsigned*)p_fth, (unsigned*)p_ftl,
        NTB, FEAT, KPAD);

    // gates_x = feats @ w_ih^T + b_ih + b_hh (fp32 out for LSTM)
    gemm_bf3p_kernel<false, false><<<dim3((4 * HID) / 128, NTB / 128), 256, GEMM_SMEM>>>(
        (const unsigned*)p_fth, (const unsigned*)p_ftl,
        (const unsigned*)p_wih_h, (const unsigned*)p_wih_l,
        bih, bhh, (float*)p_gx, nullptr, nullptr,
        NTB, 4 * HID, FEAT);

    lstm_kernel<<<NBLK, 256, LSTM_SMEM>>>(done, h0, c0, whh, out);

    heads_kernel<<<NTB / 8, 256>>>(polw, polb, valw, valb, out);
}

// round 15
// speedup vs baseline: 1.0445x; 1.0445x over previous
#include <cuda_runtime.h>
#include <cuda_bf16.h>
#include <math.h>

// ---------------- problem constants ----------------
#define TT   128
#define BB   32
#define NTB  4096            // T*B
#define HID  256
#define FEAT 512
#define FLAT 3136            // 64*7*7
#define NACT 6

// output layout: logits[4096*6], v[4096], h[32*256], c[32*256]
#define OUT_V    24576
#define OUT_H    28672
#define OUT_C    36864

// ---------------- packed f32x2 helpers (LSTM) ----------------
typedef unsigned long long u64t;
__device__ __forceinline__ u64t pk2(float lo, float hi) {
    u64t r;
    asm("mov.b64 %0, {%1, %2};" : "=l"(r) : "f"(lo), "f"(hi));
    return r;
}
__device__ __forceinline__ void fma2(u64t& d, u64t a, u64t b) {
    asm("fma.rn.f32x2 %0, %1, %2, %0;" : "+l"(d) : "l"(a), "l"(b));
}
__device__ __forceinline__ float2 upk2(u64t v) {
    float2 f;
    asm("mov.b64 {%0, %1}, %2;" : "=f"(f.x), "=f"(f.y) : "l"(v));
    return f;
}

// ---------------- bf16 helpers ----------------
__device__ __forceinline__ void mma_bf16(float c[4], const unsigned a[4],
                                         unsigned b0, unsigned b1) {
    asm volatile(
        "mma.sync.aligned.m16n8k16.row.col.f32.bf16.bf16.f32 "
        "{%0,%1,%2,%3}, {%4,%5,%6,%7}, {%8,%9}, {%0,%1,%2,%3};"
        : "+f"(c[0]), "+f"(c[1]), "+f"(c[2]), "+f"(c[3])
        : "r"(a[0]), "r"(a[1]), "r"(a[2]), "r"(a[3]), "r"(b0), "r"(b1));
}
__device__ __forceinline__ void bf_split(float x, __nv_bfloat16& h, __nv_bfloat16& l) {
    h = __float2bfloat16(x);
    l = __float2bfloat16(x - __bfloat162float(h));
}
__device__ __forceinline__ unsigned pack_bf2(__nv_bfloat16 a, __nv_bfloat16 b) {
    __nv_bfloat162 v(a, b);
    return *(unsigned*)&v;
}
__device__ __forceinline__ unsigned lo32(u64t v) { return (unsigned)v; }
__device__ __forceinline__ unsigned hi32(u64t v) { return (unsigned)(v >> 32); }

// ---------------- scratch ----------------
__device__ float g_c1[(size_t)NTB*32*20*20];
__device__ float g_c2[(size_t)NTB*64*9*9];
__device__ float g_c3[(size_t)NTB*64*7*7];
__device__ float g_feat[(size_t)NTB*FEAT];
__device__ float g_gx[(size_t)NTB*4*HID];
__device__ float g_hs[(size_t)NTB*HID];
__device__ float g_h[BB*HID];
__device__ unsigned g_bar;
__device__ unsigned g_exit;

// ======================================================================
// bf16x3 implicit-GEMM conv, hi/lo interleaved smem.
// Inner loop UNPREDICATED: thread positions clamped to NPOS-1 at setup, so
// all gathers are valid; garbage columns never stored (MMA column independence).
// ======================================================================
template<int CIN,int KW,int S,int IW,int OW,int MCH,int KC,int NG,int MAXNT,bool SCALE>
__global__ void __launch_bounds__(256, 2)
conv_bf3_kernel(const float* __restrict__ src,
                const float* __restrict__ w,
                const float* __restrict__ bias,
                float* __restrict__ dst) {
    constexpr int K    = CIN * KW * KW;
    constexpr int NPOS = OW * OW;
    constexpr int ISZ  = CIN * IW * IW;
    constexpr int NCH  = K / KC;
    constexpr int WSW  = KC + 2;
    constexpr int NTT  = (NPOS + 7) / 8;
    constexpr int IPAIR = ISZ / 2;

    extern __shared__ unsigned smw[];
    unsigned* iw = smw;                         // (IPAIR+8)*2 words
    unsigned* ww = iw + (IPAIR + 8) * 2;        // MCH*WSW words
    int* kof = (int*)(ww + MCH * WSW);          // [K]

    int n = blockIdx.x, t = threadIdx.x;

    const float* s = src + (size_t)n * ISZ;
    for (int i = t; i < IPAIR; i += 256) {
        float x0 = s[2 * i], x1 = s[2 * i + 1];
        if (SCALE) { x0 *= (1.0f / 255.0f); x1 *= (1.0f / 255.0f); }
        __nv_bfloat16 h0, l0, h1, l1;
        bf_split(x0, h0, l0);
        bf_split(x1, h1, l1);
        iw[2 * i]     = pack_bf2(h0, h1);
        iw[2 * i + 1] = pack_bf2(l0, l1);
    }
    if (t < 16) iw[IPAIR * 2 + t] = 0u;
    for (int i = t; i < K; i += 256) {
        int c = i / (KW * KW), r = i % (KW * KW);
        kof[i] = (c * IW + r / KW) * IW + (r % KW);
    }

    int wid = t >> 5, lane = t & 31;
    int gid = lane >> 2, tid4 = lane & 3;
    int wm, ng;
    if (MCH == 32) { wm = wid >> 2; ng = wid & 3; }
    else           { wm = wid >> 1; ng = wid & 1; }
    int m0 = wm * 16 + gid;

    int nbase[MAXNT];
#pragma unroll
    for (int j = 0; j < MAXNT; j++) {
        int nt = ng + j * NG;
        int p = nt * 8 + gid;
        if (p >= NPOS) p = NPOS - 1;          // clamp: always-valid gather
        int oy = p / OW, ox = p % OW;
        nbase[j] = oy * S * IW + ox * S;
    }

    float acc[MAXNT][4];
#pragma unroll
    for (int j = 0; j < MAXNT; j++)
        acc[j][0] = acc[j][1] = acc[j][2] = acc[j][3] = 0.f;

    for (int ck = 0; ck < NCH; ck++) {
        __syncthreads();
        for (int i = t; i < MCH * (KC / 2); i += 256) {
            int m = i / (KC / 2), q = i % (KC / 2);
            float x0 = w[(size_t)m * K + ck * KC + 2 * q];
            float x1 = w[(size_t)m * K + ck * KC + 2 * q + 1];
            __nv_bfloat16 h0, l0, h1, l1;
            bf_split(x0, h0, l0);
            bf_split(x1, h1, l1);
            ww[m * WSW + 2 * q]     = pack_bf2(h0, h1);
            ww[m * WSW + 2 * q + 1] = pack_bf2(l0, l1);
        }
        __syncthreads();

        for (int k16 = 0; k16 < KC / 16; k16++) {
            int wq = k16 * 8 + tid4;
            u64t A0 = *(const u64t*)&ww[m0 * WSW + 2 * wq];
            u64t A1 = *(const u64t*)&ww[(m0 + 8) * WSW + 2 * wq];
            u64t A2 = *(const u64t*)&ww[m0 * WSW + 2 * wq + 8];
            u64t A3 = *(const u64t*)&ww[(m0 + 8) * WSW + 2 * wq + 8];
            unsigned ah[4] = {lo32(A0), lo32(A1), lo32(A2), lo32(A3)};
            unsigned al[4] = {hi32(A0), hi32(A1), hi32(A2), hi32(A3)};

            int kbase = ck * KC + k16 * 16;
            int oa = kof[kbase + 2 * tid4];
            int ob = kof[kbase + 8 + 2 * tid4];
            // pairwise n-tiles, unconditional gathers
#pragma unroll
            for (int j = 0; j < MAXNT; j += 2) {
                u64t P0 = *(const u64t*)&iw[(oa + nbase[j])];
                u64t P1 = *(const u64t*)&iw[(ob + nbase[j])];
                u64t Q0 = 0, Q1 = 0;
                if (j + 1 < MAXNT) {
                    Q0 = *(const u64t*)&iw[(oa + nbase[j + 1])];
                    Q1 = *(const u64t*)&iw[(ob + nbase[j + 1])];
                }
                mma_bf16(acc[j], ah, lo32(P0), lo32(P1));
                if (j + 1 < MAXNT) mma_bf16(acc[j + 1], ah, lo32(Q0), lo32(Q1));
                mma_bf16(acc[j], ah, hi32(P0), hi32(P1));
                if (j + 1 < MAXNT) mma_bf16(acc[j + 1], ah, hi32(Q0), hi32(Q1));
                mma_bf16(acc[j], al, lo32(P0), lo32(P1));
                if (j + 1 < MAXNT) mma_bf16(acc[j + 1], al, lo32(Q0), lo32(Q1));
            }
        }
    }

    float* base = dst + (size_t)n * MCH * NPOS;
    float b0 = __ldg(&bias[m0]);
    float b1 = __ldg(&bias[m0 + 8]);
#pragma unroll
    for (int j = 0; j < MAXNT; j++) {
        int nt = ng + j * NG;
        if (nt >= NTT) continue;
        int col = nt * 8 + tid4 * 2;
        if (col < NPOS) {
            base[(size_t)m0 * NPOS + col]       = fmaxf(acc[j][0] + b0, 0.f);
            base[(size_t)(m0 + 8) * NPOS + col] = fmaxf(acc[j][2] + b1, 0.f);
        }
        if (col + 1 < NPOS) {
            base[(size_t)m0 * NPOS + col + 1]       = fmaxf(acc[j][1] + b0, 0.f);
            base[(size_t)(m0 + 8) * NPOS + col + 1] = fmaxf(acc[j][3] + b1, 0.f);
        }
    }
}

// conv1: KC=192 (single chunk).  conv2: KC=128.
#define C1B_SMEM (((21168/2 + 8) * 2 + 32 * 194) * 4 + 192 * 4)
#define C2B_SMEM (((12800/2 + 8) * 2 + 64 * 130) * 4 + 512 * 4)

// ======================================================================
// conv3 bf16x3 MMA (KW padded 3->4, dual shifted input planes),
// clamped positions, unconditional gathers.
// ======================================================================
#define C3M_ISZ   5184
#define C3M_IPAIR 2592
#define C3M_IWRDS ((C3M_IPAIR + 8) * 2)
#define C3M_WSW   194
#define C3M_SMEM  ((2 * C3M_IWRDS + 64 * C3M_WSW) * 4 + 768 * 4)
__global__ void __launch_bounds__(256, 2)
conv3_mma_kernel(const float* __restrict__ src,
                 const float* __restrict__ w,
                 const float* __restrict__ bias,
                 float* __restrict__ dst) {
    constexpr int IW = 9, OW = 7, NPOS = 49, MCH = 64;
    constexpr int K = 768, KC = 192, NCH = 4;
    constexpr int NTT = 7, NG = 2, MAXNT = 4;

    extern __shared__ unsigned smw[];
    unsigned* iw = smw;
    unsigned* jw = iw + C3M_IWRDS;
    unsigned* ww = jw + C3M_IWRDS;
    int* kof = (int*)(ww + 64 * C3M_WSW);

    int n = blockIdx.x, t = threadIdx.x;
    const float* s = src + (size_t)n * C3M_ISZ;

    for (int u = t; u < C3M_IPAIR + 8; u += 256) {
        float x0 = (2*u   < C3M_ISZ) ? s[2*u]   : 0.f;
        float x1 = (2*u+1 < C3M_ISZ) ? s[2*u+1] : 0.f;
        float x2 = (2*u+2 < C3M_ISZ) ? s[2*u+2] : 0.f;
        __nv_bfloat16 h0,l0,h1,l1,h2,l2;
        bf_split(x0,h0,l0); bf_split(x1,h1,l1); bf_split(x2,h2,l2);
        iw[2*u]   = pack_bf2(h0,h1); iw[2*u+1] = pack_bf2(l0,l1);
        jw[2*u]   = pack_bf2(h1,h2); jw[2*u+1] = pack_bf2(l1,l2);
    }
    for (int i = t; i < K; i += 256) {
        int kx = i & 3, ky = (i >> 2) % 3, c = i / 12;
        kof[i] = c * 81 + ky * 9 + kx;
    }

    int wid = t >> 5, lane = t & 31;
    int gid = lane >> 2, tid4 = lane & 3;
    int wm = wid >> 1, ng = wid & 1;
    int m0 = wm * 16 + gid;

    int nbase[MAXNT];
#pragma unroll
    for (int j = 0; j < MAXNT; j++) {
        int nt = ng + j * NG;
        int p = nt * 8 + gid;
        if (p >= NPOS) p = NPOS - 1;
        int oy = p / OW, ox = p % OW;
        nbase[j] = oy * IW + ox;
    }

    float acc[MAXNT][4];
#pragma unroll
    for (int j = 0; j < MAXNT; j++)
        acc[j][0] = acc[j][1] = acc[j][2] = acc[j][3] = 0.f;

    for (int ck = 0; ck < NCH; ck++) {
        __syncthreads();
        for (int i = t; i < MCH * (KC / 2); i += 256) {
            int m = i / (KC / 2), q = i % (KC / 2);
            int k = ck * KC + 2 * q;
            int kx = k & 3, ky = (k >> 2) % 3, c = k / 12;
            float x0 = w[((size_t)(m * 64 + c) * 3 + ky) * 3 + kx];
            float x1 = (kx == 0) ? w[((size_t)(m * 64 + c) * 3 + ky) * 3 + 1] : 0.f;
            __nv_bfloat16 h0, l0, h1, l1;
            bf_split(x0, h0, l0);
            bf_split(x1, h1, l1);
            ww[m * C3M_WSW + 2 * q]     = pack_bf2(h0, h1);
            ww[m * C3M_WSW + 2 * q + 1] = pack_bf2(l0, l1);
        }
        __syncthreads();

        for (int k16 = 0; k16 < KC / 16; k16++) {
            int wq = k16 * 8 + tid4;
            u64t A0 = *(const u64t*)&ww[m0 * C3M_WSW + 2 * wq];
            u64t A1 = *(const u64t*)&ww[(m0 + 8) * C3M_WSW + 2 * wq];
            u64t A2 = *(const u64t*)&ww[m0 * C3M_WSW + 2 * wq + 8];
            u64t A3 = *(const u64t*)&ww[(m0 + 8) * C3M_WSW + 2 * wq + 8];
            unsigned ah[4] = {lo32(A0), lo32(A1), lo32(A2), lo32(A3)};
            unsigned al[4] = {hi32(A0), hi32(A1), hi32(A2), hi32(A3)};

            int kbase = ck * KC + k16 * 16;
            int oa = kof[kbase + 2 * tid4];
            int ob = kof[kbase + 8 + 2 * tid4];
#pragma unroll
            for (int j = 0; j < MAXNT; j += 2) {
                int e0 = oa + nbase[j];
                int e1 = ob + nbase[j];
                const unsigned* pp0 = (e0 & 1) ? (jw + e0 - 1) : (iw + e0);
                const unsigned* pp1 = (e1 & 1) ? (jw + e1 - 1) : (iw + e1);
                u64t P0 = *(const u64t*)pp0;
                u64t P1 = *(const u64t*)pp1;
                int f0 = oa + nbase[j + 1];
                int f1 = ob + nbase[j + 1];
                const unsigned* qq0 = (f0 & 1) ? (jw + f0 - 1) : (iw + f0);
                const unsigned* qq1 = (f1 & 1) ? (jw + f1 - 1) : (iw + f1);
                u64t Q0 = *(const u64t*)qq0;
                u64t Q1 = *(const u64t*)qq1;
                mma_bf16(acc[j],     ah, lo32(P0), lo32(P1));
                mma_bf16(acc[j + 1], ah, lo32(Q0), lo32(Q1));
                mma_bf16(acc[j],     ah, hi32(P0), hi32(P1));
                mma_bf16(acc[j + 1], ah, hi32(Q0), hi32(Q1));
                mma_bf16(acc[j],     al, lo32(P0), lo32(P1));
                mma_bf16(acc[j + 1], al, lo32(Q0), lo32(Q1));
            }
        }
    }

    float* base = dst + (size_t)n * MCH * NPOS;
    float b0 = __ldg(&bias[m0]);
    float b1 = __ldg(&bias[m0 + 8]);
#pragma unroll
    for (int j = 0; j < MAXNT; j++) {
        int nt = ng + j * NG;
        if (nt >= NTT) continue;
        int col = nt * 8 + tid4 * 2;
        if (col < NPOS) {
            base[(size_t)m0 * NPOS + col]       = fmaxf(acc[j][0] + b0, 0.f);
            base[(size_t)(m0 + 8) * NPOS + col] = fmaxf(acc[j][2] + b1, 0.f);
        }
        if (col + 1 < NPOS) {
            base[(size_t)m0 * NPOS + col + 1]       = fmaxf(acc[j][1] + b0, 0.f);
            base[(size_t)(m0 + 8) * NPOS + col + 1] = fmaxf(acc[j][3] + b1, 0.f);
        }
    }
}

// ======================================================================
// bf16x3 GEMM (round-12 champion): separate hi/lo planes, cvt at fill,
// term-major MMA order, double-buffered.
// ======================================================================
#define GEMM_SMEM 49152
template <bool RELU>
__global__ void __launch_bounds__(256)
gemm_bf3_kernel(const float* __restrict__ A,
                const float* __restrict__ Bw,
                const float* __restrict__ bias1,
                const float* __restrict__ bias2,
                float* __restrict__ C,
                int M, int N, int K) {
    extern __shared__ __nv_bfloat16 gsm[];
    __nv_bfloat16* Ah = gsm;            // [2][128][24]
    __nv_bfloat16* Al = gsm + 6144;
    __nv_bfloat16* Bh = gsm + 12288;
    __nv_bfloat16* Bl = gsm + 18432;

    int bm = blockIdx.y * 128, bn = blockIdx.x * 128;
    int t = threadIdx.x;
    int wid = t >> 5, lane = t & 31;
    int gid = lane >> 2, tid4 = lane & 3;
    int wm = (wid >> 1) * 32;
    int wn = (wid & 1) * 64;
    int lr = t >> 1, lc = (t & 1) * 8;

    float c[2][8][4];
#pragma unroll
    for (int mt = 0; mt < 2; mt++)
#pragma unroll
        for (int nt = 0; nt < 8; nt++)
#pragma unroll
            for (int q = 0; q < 4; q++) c[mt][nt][q] = 0.f;

    const float* Ap = A + (size_t)(bm + lr) * K + lc;
    const float* Bp = Bw + (size_t)(bn + lr) * K + lc;

    auto fill = [&](__nv_bfloat16* dh, __nv_bfloat16* dl,
                    float4 f0, float4 f1) {
        float v[8] = {f0.x, f0.y, f0.z, f0.w, f1.x, f1.y, f1.z, f1.w};
        unsigned hw[4], lw[4];
#pragma unroll
        for (int i = 0; i < 4; i++) {
            __nv_bfloat16 h0, l0, h1, l1;
            bf_split(v[2*i], h0, l0);
            bf_split(v[2*i+1], h1, l1);
            hw[i] = pack_bf2(h0, h1);
            lw[i] = pack_bf2(l0, l1);
        }
        *(uint4*)dh = make_uint4(hw[0], hw[1], hw[2], hw[3]);
        *(uint4*)dl = make_uint4(lw[0], lw[1], lw[2], lw[3]);
    };

    {
        float4 a0 = *(const float4*)(Ap);
        float4 a1 = *(const float4*)(Ap + 4);
        float4 b0 = *(const float4*)(Bp);
        float4 b1 = *(const float4*)(Bp + 4);
        fill(Ah + lr * 24 + lc, Al + lr * 24 + lc, a0, a1);
        fill(Bh + lr * 24 + lc, Bl + lr * 24 + lc, b0, b1);
    }
    __syncthreads();

    int cur = 0;
    for (int k0 = 0; k0 < K; k0 += 16) {
        bool more = (k0 + 16) < K;
        float4 ga0, ga1, gb0, gb1;
        if (more) {
            ga0 = *(const float4*)(Ap + k0 + 16);
            ga1 = *(const float4*)(Ap + k0 + 20);
            gb0 = *(const float4*)(Bp + k0 + 16);
            gb1 = *(const float4*)(Bp + k0 + 20);
        }
        const unsigned* ahw = (const unsigned*)(Ah + cur * 3072);
        const unsigned* alw = (const unsigned*)(Al + cur * 3072);
        const unsigned* bhw = (const unsigned*)(Bh + cur * 3072);
        const unsigned* blw = (const unsigned*)(Bl + cur * 3072);
        unsigned afh[2][4], afl[2][4];
#pragma unroll
        for (int mt = 0; mt < 2; mt++) {
            int m = wm + mt * 16 + gid;
            afh[mt][0] = ahw[m * 12 + tid4];
            afh[mt][1] = ahw[(m + 8) * 12 + tid4];
            afh[mt][2] = ahw[m * 12 + tid4 + 4];
            afh[mt][3] = ahw[(m + 8) * 12 + tid4 + 4];
            afl[mt][0] = alw[m * 12 + tid4];
            afl[mt][1] = alw[(m + 8) * 12 + tid4];
            afl[mt][2] = alw[m * 12 + tid4 + 4];
            afl[mt][3] = alw[(m + 8) * 12 + tid4 + 4];
        }
        unsigned bfh[8][2], bfl[8][2];
#pragma unroll
        for (int nt = 0; nt < 8; nt++) {
            int nn = wn + nt * 8 + gid;
            bfh[nt][0] = bhw[nn * 12 + tid4];
            bfh[nt][1] = bhw[nn * 12 + tid4 + 4];
            bfl[nt][0] = blw[nn * 12 + tid4];
            bfl[nt][1] = blw[nn * 12 + tid4 + 4];
        }
#pragma unroll
        for (int mt = 0; mt < 2; mt++)
#pragma unroll
            for (int nt = 0; nt < 8; nt++)
                mma_bf16(c[mt][nt], afh[mt], bfh[nt][0], bfh[nt][1]);
#pragma unroll
        for (int mt = 0; mt < 2; mt++)
#pragma unroll
            for (int nt = 0; nt < 8; nt++)
                mma_bf16(c[mt][nt], afh[mt], bfl[nt][0], bfl[nt][1]);
#pragma unroll
        for (int mt = 0; mt < 2; mt++)
#pragma unroll
            for (int nt = 0; nt < 8; nt++)
                mma_bf16(c[mt][nt], afl[mt], bfh[nt][0], bfh[nt][1]);
        if (more) {
            int nxt = cur ^ 1;
            fill(Ah + nxt * 3072 + lr * 24 + lc, Al + nxt * 3072 + lr * 24 + lc, ga0, ga1);
            fill(Bh + nxt * 3072 + lr * 24 + lc, Bl + nxt * 3072 + lr * 24 + lc, gb0, gb1);
            __syncthreads();
            cur = nxt;
        }
    }

#pragma unroll
    for (int mt = 0; mt < 2; mt++) {
        int row = bm + wm + mt * 16 + gid;
#pragma unroll
        for (int nt = 0; nt < 8; nt++) {
            int col = bn + wn + nt * 8 + tid4 * 2;
            float bv0 = bias1[col], bv1 = bias1[col + 1];
            if (bias2) { bv0 += bias2[col]; bv1 += bias2[col + 1]; }
            float r0 = c[mt][nt][0] + bv0;
            float r1 = c[mt][nt][1] + bv1;
            float r2 = c[mt][nt][2] + bv0;
            float r3 = c[mt][nt][3] + bv1;
            if (RELU) {
                r0 = fmaxf(r0, 0.f); r1 = fmaxf(r1, 0.f);
                r2 = fmaxf(r2, 0.f); r3 = fmaxf(r3, 0.f);
            }
            *(float2*)&C[(size_t)row * N + col]       = make_float2(r0, r1);
            *(float2*)&C[(size_t)(row + 8) * N + col] = make_float2(r2, r3);
        }
    }
}

// ======================================================================
// persistent LSTM: 128 CTAs, each owns 2 hidden units.  (proven)
// ======================================================================
#define NBLK 128
#define LSTM_SMEM ((2048 + 8224 + 64 + 576) * 4)
__device__ __forceinline__ float sigmoidf(float x) { return 1.f / (1.f + expf(-x)); }

__global__ void __launch_bounds__(256)
lstm_kernel(const float* __restrict__ done,
            const float* __restrict__ h0,
            const float* __restrict__ c0,
            const float* __restrict__ whh,
            float* __restrict__ out) {
    extern __shared__ float sm[];
    float* w_s = sm;             // [k=256][r=8]
    float* h_s = sm + 2048;      // [32][257]
    float* c_s = h_s + 8224;     // [64]
    float* p_s = c_s + 64;       // [2][32][9]
    int t = threadIdx.x, blk = blockIdx.x;
    int j0 = blk * 2;

    for (int i = t; i < 2048; i += 256) {
        int k = i >> 3, r = i & 7;
        int q = r >> 1, jj = r & 1;
        w_s[i] = whh[(size_t)(q * HID + j0 + jj) * HID + k];
    }
    if (t < 64) {
        int b = t >> 1, jj = t & 1;
        c_s[t] = c0[b * HID + j0 + jj];
    }
    __syncthreads();

    int u = t & 127, half = t >> 7;
    int gb = u & 31, rq = u >> 5;
    unsigned target = 0;

    for (int step = 0; step < TT; step++) {
        float2 acc0;
        if (half == 0)
            acc0 = *(const float2*)&g_gx[(size_t)(step * BB + gb) * 4 * HID + rq * HID + j0];
        else
            acc0 = make_float2(0.f, 0.f);
        u64t accp = pk2(acc0.x, acc0.y);

        const float* hsrc = (step == 0) ? h0 : g_h;
        for (int i = t; i < BB * HID; i += 256) {
            int b = i >> 8;
            h_s[b * 257 + (i & 255)] = hsrc[i] * (1.0f - __ldg(&done[step * BB + b]));
        }
        __syncthreads();

        {
            const float* hp = &h_s[gb * 257 + half * 128];
            const float* wp = &w_s[(half * 128) * 8 + rq * 2];
#pragma unroll 8
            for (int k = 0; k < 128; k++) {
                float hv = hp[k];
                u64t hh = pk2(hv, hv);
                u64t wv = *(const u64t*)&wp[k * 8];
                fma2(accp, hh, wv);
            }
            float2 r = upk2(accp);
            float* pp = &p_s[half * 288 + gb * 9 + rq * 2];
            pp[0] = r.x; pp[1] = r.y;
        }
        __syncthreads();

        if (t < 64) {
            int b = t >> 1, jj = t & 1;
            float m = 1.0f - __ldg(&done[step * BB + b]);
            const float* p0 = &p_s[b * 9];
            const float* p1 = &p_s[288 + b * 9];
            float gi = p0[0 + jj] + p1[0 + jj];
            float gf = p0[2 + jj] + p1[2 + jj];
            float gg = p0[4 + jj] + p1[4 + jj];
            float go = p0[6 + jj] + p1[6 + jj];
            float I = sigmoidf(gi);
            float F = sigmoidf(gf);
            float G = tanhf(gg);
            float O = sigmoidf(go);
            float c_new = F * (m * c_s[t]) + I * G;
            c_s[t] = c_new;
            float h_new = O * tanhf(c_new);
            g_h[b * HID + j0 + jj] = h_new;
            g_hs[(size_t)(step * BB + b) * HID + j0 + jj] = h_new;
            if (step == TT - 1) {
                out[OUT_H + b * HID + j0 + jj] = h_new;
                out[OUT_C + b * HID + j0 + jj] = c_new;
            }
        }
        __threadfence();
        __syncthreads();
        if (t == 0) {
            atomicAdd(&g_bar, 1u);
            target += NBLK;
            while (*(volatile unsigned*)&g_bar < target) { }
        }
        __syncthreads();
    }

    if (t == 0) {
        unsigned v = atomicAdd(&g_exit, 1u);
        if (v == NBLK - 1) {
            atomicExch(&g_exit, 0u);
            atomicExch(&g_bar, 0u);
            __threadfence();
        }
    }
}

// ======================================================================
// heads
// ======================================================================
__global__ void heads_kernel(const float* __restrict__ pw,
                             const float* __restrict__ pb,
                             const float* __restrict__ vw,
                             const float* __restrict__ vb,
                             float* __restrict__ out) {
    __shared__ float ws[7 * 256];
    int t = threadIdx.x;
    for (int i = t; i < 6 * 256; i += 256) ws[i] = pw[i];
    if (t < 256) ws[1536 + t] = vw[t];
    __syncthreads();

    int warp = t >> 5, lane = t & 31;
    int row = blockIdx.x * 8 + warp;
    const float* hrow = g_hs + (size_t)row * 256;
    float p[7];
#pragma unroll
    for (int a = 0; a < 7; a++) p[a] = 0.f;
    for (int k = lane; k < 256; k += 32) {
        float hv = hrow[k];
#pragma unroll
        for (int a = 0; a < 7; a++) p[a] += hv * ws[a * 256 + k];
    }
#pragma unroll
    for (int a = 0; a < 7; a++)
#pragma unroll
        for (int off = 16; off; off >>= 1)
            p[a] += __shfl_xor_sync(0xffffffffu, p[a], off);
    if (lane == 0) {
#pragma unroll
        for (int a = 0; a < 6; a++) out[(size_t)row * 6 + a] = p[a] + pb[a];
        out[OUT_V + row] = p[6] + vb[0];
    }
}

// ======================================================================
// launch
// ======================================================================
extern "C" void kernel_launch(void* const* d_in, const int* in_sizes, int n_in,
                              void* d_out, int out_size) {
    const float* image = (const float*)d_in[0];
    const float* done  = (const float*)d_in[1];
    const float* h0    = (const float*)d_in[2];
    const float* c0    = (const float*)d_in[3];
    const float* c1w   = (const float*)d_in[4];
    const float* c1b   = (const float*)d_in[5];
    const float* c2w   = (const float*)d_in[6];
    const float* c2b   = (const float*)d_in[7];
    const float* c3w   = (const float*)d_in[8];
    const float* c3b   = (const float*)d_in[9];
    const float* fcw   = (const float*)d_in[10];
    const float* fcb   = (const float*)d_in[11];
    const float* wih   = (const float*)d_in[12];
    const float* whh   = (const float*)d_in[13];
    const float* bih   = (const float*)d_in[14];
    const float* bhh   = (const float*)d_in[15];
    const float* polw  = (const float*)d_in[16];
    const float* polb  = (const float*)d_in[17];
    const float* valw  = (const float*)d_in[18];
    const float* valb  = (const float*)d_in[19];
    float* out = (float*)d_out;

    auto conv1 = conv_bf3_kernel<3, 8, 4, 84, 20, 32, 192, 4, 13, true>;
    auto conv2 = conv_bf3_kernel<32, 4, 2, 20, 9,  64, 128, 2, 6,  false>;

    cudaFuncSetAttribute(conv1, cudaFuncAttributeMaxDynamicSharedMemorySize, C1B_SMEM);
    cudaFuncSetAttribute(conv2, cudaFuncAttributeMaxDynamicSharedMemorySize, C2B_SMEM);
    cudaFuncSetAttribute(conv3_mma_kernel, cudaFuncAttributeMaxDynamicSharedMemorySize, C3M_SMEM);
    cudaFuncSetAttribute(gemm_bf3_kernel<true>,  cudaFuncAttributeMaxDynamicSharedMemorySize, GEMM_SMEM);
    cudaFuncSetAttribute(gemm_bf3_kernel<false>, cudaFuncAttributeMaxDynamicSharedMemorySize, GEMM_SMEM);
    cudaFuncSetAttribute(lstm_kernel, cudaFuncAttributeMaxDynamicSharedMemorySize, LSTM_SMEM);

    void *p_c1, *p_c2, *p_c3, *p_feat, *p_gx;
    cudaGetSymbolAddress(&p_c1, g_c1);
    cudaGetSymbolAddress(&p_c2, g_c2);
    cudaGetSymbolAddress(&p_c3, g_c3);
    cudaGetSymbolAddress(&p_feat, g_feat);
    cudaGetSymbolAddress(&p_gx, g_gx);

    conv1<<<NTB, 256, C1B_SMEM>>>(image, c1w, c1b, (float*)p_c1);
    conv2<<<NTB, 256, C2B_SMEM>>>((const float*)p_c1, c2w, c2b, (float*)p_c2);
    conv3_mma_kernel<<<NTB, 256, C3M_SMEM>>>((const float*)p_c2, c3w, c3b, (float*)p_c3);

    // feats = relu(flat @ fc_w^T + fc_b)   [4096,512]  (bf16x3 ~= fp32)
    gemm_bf3_kernel<true><<<dim3(FEAT / 128, NTB / 128), 256, GEMM_SMEM>>>(
        (const float*)p_c3, fcw, fcb, nullptr, (float*)p_feat, NTB, FEAT, FLAT);

    // gates_x = feats @ w_ih^T + b_ih + b_hh   [4096,1024]  (bf16x3 ~= fp32)
    gemm_bf3_kernel<false><<<dim3((4 * HID) / 128, NTB / 128), 256, GEMM_SMEM>>>(
        (const float*)p_feat, wih, bih, bhh, (float*)p_gx, NTB, 4 * HID, FEAT);

    lstm_kernel<<<NBLK, 256, LSTM_SMEM>>>(done, h0, c0, whh, out);

    heads_kernel<<<NTB / 8, 256>>>(polw, polb, valw, valb, out);
}

// round 16
// speedup vs baseline: 1.1657x; 1.1160x over previous
#include <cuda_runtime.h>
#include <cuda_bf16.h>
#include <math.h>

// ---------------- problem constants ----------------
#define TT   128
#define BB   32
#define NTB  4096            // T*B
#define HID  256
#define FEAT 512
#define FLAT 3136            // 64*7*7
#define NACT 6

// output layout: logits[4096*6], v[4096], h[32*256], c[32*256]
#define OUT_V    24576
#define OUT_H    28672
#define OUT_C    36864

// ---------------- packed f32x2 helpers (LSTM) ----------------
typedef unsigned long long u64t;
__device__ __forceinline__ u64t pk2(float lo, float hi) {
    u64t r;
    asm("mov.b64 %0, {%1, %2};" : "=l"(r) : "f"(lo), "f"(hi));
    return r;
}
__device__ __forceinline__ void fma2(u64t& d, u64t a, u64t b) {
    asm("fma.rn.f32x2 %0, %1, %2, %0;" : "+l"(d) : "l"(a), "l"(b));
}
__device__ __forceinline__ float2 upk2(u64t v) {
    float2 f;
    asm("mov.b64 {%0, %1}, %2;" : "=f"(f.x), "=f"(f.y) : "l"(v));
    return f;
}

// ---------------- bf16 helpers ----------------
__device__ __forceinline__ void mma_bf16(float c[4], const unsigned a[4],
                                         unsigned b0, unsigned b1) {
    asm volatile(
        "mma.sync.aligned.m16n8k16.row.col.f32.bf16.bf16.f32 "
        "{%0,%1,%2,%3}, {%4,%5,%6,%7}, {%8,%9}, {%0,%1,%2,%3};"
        : "+f"(c[0]), "+f"(c[1]), "+f"(c[2]), "+f"(c[3])
        : "r"(a[0]), "r"(a[1]), "r"(a[2]), "r"(a[3]), "r"(b0), "r"(b1));
}
__device__ __forceinline__ void bf_split(float x, __nv_bfloat16& h, __nv_bfloat16& l) {
    h = __float2bfloat16(x);
    l = __float2bfloat16(x - __bfloat162float(h));
}
__device__ __forceinline__ unsigned pack_bf2(__nv_bfloat16 a, __nv_bfloat16 b) {
    __nv_bfloat162 v(a, b);
    return *(unsigned*)&v;
}
__device__ __forceinline__ unsigned lo32(u64t v) { return (unsigned)v; }
__device__ __forceinline__ unsigned hi32(u64t v) { return (unsigned)(v >> 32); }

// ---------------- scratch ----------------
__device__ float g_c1[(size_t)NTB*32*20*20];
__device__ float g_c2[(size_t)NTB*64*9*9];
__device__ float g_c3[(size_t)NTB*64*7*7];
__device__ float g_feat[(size_t)NTB*FEAT];
__device__ float g_gx[(size_t)NTB*4*HID];
__device__ float g_hs[(size_t)NTB*HID];
__device__ float g_h[BB*HID];
__device__ unsigned g_bar;
__device__ unsigned g_exit;

// ======================================================================
// bf16x3 implicit-GEMM conv (round-15 champion, unchanged).
// ======================================================================
template<int CIN,int KW,int S,int IW,int OW,int MCH,int KC,int NG,int MAXNT,bool SCALE>
__global__ void __launch_bounds__(256, 2)
conv_bf3_kernel(const float* __restrict__ src,
                const float* __restrict__ w,
                const float* __restrict__ bias,
                float* __restrict__ dst) {
    constexpr int K    = CIN * KW * KW;
    constexpr int NPOS = OW * OW;
    constexpr int ISZ  = CIN * IW * IW;
    constexpr int NCH  = K / KC;
    constexpr int WSW  = KC + 2;
    constexpr int NTT  = (NPOS + 7) / 8;
    constexpr int IPAIR = ISZ / 2;

    extern __shared__ unsigned smw[];
    unsigned* iw = smw;                         // (IPAIR+8)*2 words
    unsigned* ww = iw + (IPAIR + 8) * 2;        // MCH*WSW words
    int* kof = (int*)(ww + MCH * WSW);          // [K]

    int n = blockIdx.x, t = threadIdx.x;

    const float* s = src + (size_t)n * ISZ;
    for (int i = t; i < IPAIR; i += 256) {
        float x0 = s[2 * i], x1 = s[2 * i + 1];
        if (SCALE) { x0 *= (1.0f / 255.0f); x1 *= (1.0f / 255.0f); }
        __nv_bfloat16 h0, l0, h1, l1;
        bf_split(x0, h0, l0);
        bf_split(x1, h1, l1);
        iw[2 * i]     = pack_bf2(h0, h1);
        iw[2 * i + 1] = pack_bf2(l0, l1);
    }
    if (t < 16) iw[IPAIR * 2 + t] = 0u;
    for (int i = t; i < K; i += 256) {
        int c = i / (KW * KW), r = i % (KW * KW);
        kof[i] = (c * IW + r / KW) * IW + (r % KW);
    }

    int wid = t >> 5, lane = t & 31;
    int gid = lane >> 2, tid4 = lane & 3;
    int wm, ng;
    if (MCH == 32) { wm = wid >> 2; ng = wid & 3; }
    else           { wm = wid >> 1; ng = wid & 1; }
    int m0 = wm * 16 + gid;

    int nbase[MAXNT];
#pragma unroll
    for (int j = 0; j < MAXNT; j++) {
        int nt = ng + j * NG;
        int p = nt * 8 + gid;
        if (p >= NPOS) p = NPOS - 1;          // clamp: always-valid gather
        int oy = p / OW, ox = p % OW;
        nbase[j] = oy * S * IW + ox * S;
    }

    float acc[MAXNT][4];
#pragma unroll
    for (int j = 0; j < MAXNT; j++)
        acc[j][0] = acc[j][1] = acc[j][2] = acc[j][3] = 0.f;

    for (int ck = 0; ck < NCH; ck++) {
        __syncthreads();
        for (int i = t; i < MCH * (KC / 2); i += 256) {
            int m = i / (KC / 2), q = i % (KC / 2);
            float x0 = w[(size_t)m * K + ck * KC + 2 * q];
            float x1 = w[(size_t)m * K + ck * KC + 2 * q + 1];
            __nv_bfloat16 h0, l0, h1, l1;
            bf_split(x0, h0, l0);
            bf_split(x1, h1, l1);
            ww[m * WSW + 2 * q]     = pack_bf2(h0, h1);
            ww[m * WSW + 2 * q + 1] = pack_bf2(l0, l1);
        }
        __syncthreads();

        for (int k16 = 0; k16 < KC / 16; k16++) {
            int wq = k16 * 8 + tid4;
            u64t A0 = *(const u64t*)&ww[m0 * WSW + 2 * wq];
            u64t A1 = *(const u64t*)&ww[(m0 + 8) * WSW + 2 * wq];
            u64t A2 = *(const u64t*)&ww[m0 * WSW + 2 * wq + 8];
            u64t A3 = *(const u64t*)&ww[(m0 + 8) * WSW + 2 * wq + 8];
            unsigned ah[4] = {lo32(A0), lo32(A1), lo32(A2), lo32(A3)};
            unsigned al[4] = {hi32(A0), hi32(A1), hi32(A2), hi32(A3)};

            int kbase = ck * KC + k16 * 16;
            int oa = kof[kbase + 2 * tid4];
            int ob = kof[kbase + 8 + 2 * tid4];
#pragma unroll
            for (int j = 0; j < MAXNT; j += 2) {
                u64t P0 = *(const u64t*)&iw[(oa + nbase[j])];
                u64t P1 = *(const u64t*)&iw[(ob + nbase[j])];
                u64t Q0 = 0, Q1 = 0;
                if (j + 1 < MAXNT) {
                    Q0 = *(const u64t*)&iw[(oa + nbase[j + 1])];
                    Q1 = *(const u64t*)&iw[(ob + nbase[j + 1])];
                }
                mma_bf16(acc[j], ah, lo32(P0), lo32(P1));
                if (j + 1 < MAXNT) mma_bf16(acc[j + 1], ah, lo32(Q0), lo32(Q1));
                mma_bf16(acc[j], ah, hi32(P0), hi32(P1));
                if (j + 1 < MAXNT) mma_bf16(acc[j + 1], ah, hi32(Q0), hi32(Q1));
                mma_bf16(acc[j], al, lo32(P0), lo32(P1));
                if (j + 1 < MAXNT) mma_bf16(acc[j + 1], al, lo32(Q0), lo32(Q1));
            }
        }
    }

    float* base = dst + (size_t)n * MCH * NPOS;
    float b0 = __ldg(&bias[m0]);
    float b1 = __ldg(&bias[m0 + 8]);
#pragma unroll
    for (int j = 0; j < MAXNT; j++) {
        int nt = ng + j * NG;
        if (nt >= NTT) continue;
        int col = nt * 8 + tid4 * 2;
        if (col < NPOS) {
            base[(size_t)m0 * NPOS + col]       = fmaxf(acc[j][0] + b0, 0.f);
            base[(size_t)(m0 + 8) * NPOS + col] = fmaxf(acc[j][2] + b1, 0.f);
        }
        if (col + 1 < NPOS) {
            base[(size_t)m0 * NPOS + col + 1]       = fmaxf(acc[j][1] + b0, 0.f);
            base[(size_t)(m0 + 8) * NPOS + col + 1] = fmaxf(acc[j][3] + b1, 0.f);
        }
    }
}

// conv1: KC=192 (single chunk).  conv2: KC=128.
#define C1B_SMEM (((21168/2 + 8) * 2 + 32 * 194) * 4 + 192 * 4)
#define C2B_SMEM (((12800/2 + 8) * 2 + 64 * 130) * 4 + 512 * 4)

// ======================================================================
// conv3 bf16x3 MMA (round-15 champion, unchanged).
// ======================================================================
#define C3M_ISZ   5184
#define C3M_IPAIR 2592
#define C3M_IWRDS ((C3M_IPAIR + 8) * 2)
#define C3M_WSW   194
#define C3M_SMEM  ((2 * C3M_IWRDS + 64 * C3M_WSW) * 4 + 768 * 4)
__global__ void __launch_bounds__(256, 2)
conv3_mma_kernel(const float* __restrict__ src,
                 const float* __restrict__ w,
                 const float* __restrict__ bias,
                 float* __restrict__ dst) {
    constexpr int IW = 9, OW = 7, NPOS = 49, MCH = 64;
    constexpr int K = 768, KC = 192, NCH = 4;
    constexpr int NTT = 7, NG = 2, MAXNT = 4;

    extern __shared__ unsigned smw[];
    unsigned* iw = smw;
    unsigned* jw = iw + C3M_IWRDS;
    unsigned* ww = jw + C3M_IWRDS;
    int* kof = (int*)(ww + 64 * C3M_WSW);

    int n = blockIdx.x, t = threadIdx.x;
    const float* s = src + (size_t)n * C3M_ISZ;

    for (int u = t; u < C3M_IPAIR + 8; u += 256) {
        float x0 = (2*u   < C3M_ISZ) ? s[2*u]   : 0.f;
        float x1 = (2*u+1 < C3M_ISZ) ? s[2*u+1] : 0.f;
        float x2 = (2*u+2 < C3M_ISZ) ? s[2*u+2] : 0.f;
        __nv_bfloat16 h0,l0,h1,l1,h2,l2;
        bf_split(x0,h0,l0); bf_split(x1,h1,l1); bf_split(x2,h2,l2);
        iw[2*u]   = pack_bf2(h0,h1); iw[2*u+1] = pack_bf2(l0,l1);
        jw[2*u]   = pack_bf2(h1,h2); jw[2*u+1] = pack_bf2(l1,l2);
    }
    for (int i = t; i < K; i += 256) {
        int kx = i & 3, ky = (i >> 2) % 3, c = i / 12;
        kof[i] = c * 81 + ky * 9 + kx;
    }

    int wid = t >> 5, lane = t & 31;
    int gid = lane >> 2, tid4 = lane & 3;
    int wm = wid >> 1, ng = wid & 1;
    int m0 = wm * 16 + gid;

    int nbase[MAXNT];
#pragma unroll
    for (int j = 0; j < MAXNT; j++) {
        int nt = ng + j * NG;
        int p = nt * 8 + gid;
        if (p >= NPOS) p = NPOS - 1;
        int oy = p / OW, ox = p % OW;
        nbase[j] = oy * IW + ox;
    }

    float acc[MAXNT][4];
#pragma unroll
    for (int j = 0; j < MAXNT; j++)
        acc[j][0] = acc[j][1] = acc[j][2] = acc[j][3] = 0.f;

    for (int ck = 0; ck < NCH; ck++) {
        __syncthreads();
        for (int i = t; i < MCH * (KC / 2); i += 256) {
            int m = i / (KC / 2), q = i % (KC / 2);
            int k = ck * KC + 2 * q;
            int kx = k & 3, ky = (k >> 2) % 3, c = k / 12;
            float x0 = w[((size_t)(m * 64 + c) * 3 + ky) * 3 + kx];
            float x1 = (kx == 0) ? w[((size_t)(m * 64 + c) * 3 + ky) * 3 + 1] : 0.f;
            __nv_bfloat16 h0, l0, h1, l1;
            bf_split(x0, h0, l0);
            bf_split(x1, h1, l1);
            ww[m * C3M_WSW + 2 * q]     = pack_bf2(h0, h1);
            ww[m * C3M_WSW + 2 * q + 1] = pack_bf2(l0, l1);
        }
        __syncthreads();

        for (int k16 = 0; k16 < KC / 16; k16++) {
            int wq = k16 * 8 + tid4;
            u64t A0 = *(const u64t*)&ww[m0 * C3M_WSW + 2 * wq];
            u64t A1 = *(const u64t*)&ww[(m0 + 8) * C3M_WSW + 2 * wq];
            u64t A2 = *(const u64t*)&ww[m0 * C3M_WSW + 2 * wq + 8];
            u64t A3 = *(const u64t*)&ww[(m0 + 8) * C3M_WSW + 2 * wq + 8];
            unsigned ah[4] = {lo32(A0), lo32(A1), lo32(A2), lo32(A3)};
            unsigned al[4] = {hi32(A0), hi32(A1), hi32(A2), hi32(A3)};

            int kbase = ck * KC + k16 * 16;
            int oa = kof[kbase + 2 * tid4];
            int ob = kof[kbase + 8 + 2 * tid4];
#pragma unroll
            for (int j = 0; j < MAXNT; j += 2) {
                int e0 = oa + nbase[j];
                int e1 = ob + nbase[j];
                const unsigned* pp0 = (e0 & 1) ? (jw + e0 - 1) : (iw + e0);
                const unsigned* pp1 = (e1 & 1) ? (jw + e1 - 1) : (iw + e1);
                u64t P0 = *(const u64t*)pp0;
                u64t P1 = *(const u64t*)pp1;
                int f0 = oa + nbase[j + 1];
                int f1 = ob + nbase[j + 1];
                const unsigned* qq0 = (f0 & 1) ? (jw + f0 - 1) : (iw + f0);
                const unsigned* qq1 = (f1 & 1) ? (jw + f1 - 1) : (iw + f1);
                u64t Q0 = *(const u64t*)qq0;
                u64t Q1 = *(const u64t*)qq1;
                mma_bf16(acc[j],     ah, lo32(P0), lo32(P1));
                mma_bf16(acc[j + 1], ah, lo32(Q0), lo32(Q1));
                mma_bf16(acc[j],     ah, hi32(P0), hi32(P1));
                mma_bf16(acc[j + 1], ah, hi32(Q0), hi32(Q1));
                mma_bf16(acc[j],     al, lo32(P0), lo32(P1));
                mma_bf16(acc[j + 1], al, lo32(Q0), lo32(Q1));
            }
        }
    }

    float* base = dst + (size_t)n * MCH * NPOS;
    float b0 = __ldg(&bias[m0]);
    float b1 = __ldg(&bias[m0 + 8]);
#pragma unroll
    for (int j = 0; j < MAXNT; j++) {
        int nt = ng + j * NG;
        if (nt >= NTT) continue;
        int col = nt * 8 + tid4 * 2;
        if (col < NPOS) {
            base[(size_t)m0 * NPOS + col]       = fmaxf(acc[j][0] + b0, 0.f);
            base[(size_t)(m0 + 8) * NPOS + col] = fmaxf(acc[j][2] + b1, 0.f);
        }
        if (col + 1 < NPOS) {
            base[(size_t)m0 * NPOS + col + 1]       = fmaxf(acc[j][1] + b0, 0.f);
            base[(size_t)(m0 + 8) * NPOS + col + 1] = fmaxf(acc[j][3] + b1, 0.f);
        }
    }
}

// ======================================================================
// bf16x3 GEMM (round-12/15 champion, unchanged).
// ======================================================================
#define GEMM_SMEM 49152
template <bool RELU>
__global__ void __launch_bounds__(256)
gemm_bf3_kernel(const float* __restrict__ A,
                const float* __restrict__ Bw,
                const float* __restrict__ bias1,
                const float* __restrict__ bias2,
                float* __restrict__ C,
                int M, int N, int K) {
    extern __shared__ __nv_bfloat16 gsm[];
    __nv_bfloat16* Ah = gsm;            // [2][128][24]
    __nv_bfloat16* Al = gsm + 6144;
    __nv_bfloat16* Bh = gsm + 12288;
    __nv_bfloat16* Bl = gsm + 18432;

    int bm = blockIdx.y * 128, bn = blockIdx.x * 128;
    int t = threadIdx.x;
    int wid = t >> 5, lane = t & 31;
    int gid = lane >> 2, tid4 = lane & 3;
    int wm = (wid >> 1) * 32;
    int wn = (wid & 1) * 64;
    int lr = t >> 1, lc = (t & 1) * 8;

    float c[2][8][4];
#pragma unroll
    for (int mt = 0; mt < 2; mt++)
#pragma unroll
        for (int nt = 0; nt < 8; nt++)
#pragma unroll
            for (int q = 0; q < 4; q++) c[mt][nt][q] = 0.f;

    const float* Ap = A + (size_t)(bm + lr) * K + lc;
    const float* Bp = Bw + (size_t)(bn + lr) * K + lc;

    auto fill = [&](__nv_bfloat16* dh, __nv_bfloat16* dl,
                    float4 f0, float4 f1) {
        float v[8] = {f0.x, f0.y, f0.z, f0.w, f1.x, f1.y, f1.z, f1.w};
        unsigned hw[4], lw[4];
#pragma unroll
        for (int i = 0; i < 4; i++) {
            __nv_bfloat16 h0, l0, h1, l1;
            bf_split(v[2*i], h0, l0);
            bf_split(v[2*i+1], h1, l1);
            hw[i] = pack_bf2(h0, h1);
            lw[i] = pack_bf2(l0, l1);
        }
        *(uint4*)dh = make_uint4(hw[0], hw[1], hw[2], hw[3]);
        *(uint4*)dl = make_uint4(lw[0], lw[1], lw[2], lw[3]);
    };

    {
        float4 a0 = *(const float4*)(Ap);
        float4 a1 = *(const float4*)(Ap + 4);
        float4 b0 = *(const float4*)(Bp);
        float4 b1 = *(const float4*)(Bp + 4);
        fill(Ah + lr * 24 + lc, Al + lr * 24 + lc, a0, a1);
        fill(Bh + lr * 24 + lc, Bl + lr * 24 + lc, b0, b1);
    }
    __syncthreads();

    int cur = 0;
    for (int k0 = 0; k0 < K; k0 += 16) {
        bool more = (k0 + 16) < K;
        float4 ga0, ga1, gb0, gb1;
        if (more) {
            ga0 = *(const float4*)(Ap + k0 + 16);
            ga1 = *(const float4*)(Ap + k0 + 20);
            gb0 = *(const float4*)(Bp + k0 + 16);
            gb1 = *(const float4*)(Bp + k0 + 20);
        }
        const unsigned* ahw = (const unsigned*)(Ah + cur * 3072);
        const unsigned* alw = (const unsigned*)(Al + cur * 3072);
        const unsigned* bhw = (const unsigned*)(Bh + cur * 3072);
        const unsigned* blw = (const unsigned*)(Bl + cur * 3072);
        unsigned afh[2][4], afl[2][4];
#pragma unroll
        for (int mt = 0; mt < 2; mt++) {
            int m = wm + mt * 16 + gid;
            afh[mt][0] = ahw[m * 12 + tid4];
            afh[mt][1] = ahw[(m + 8) * 12 + tid4];
            afh[mt][2] = ahw[m * 12 + tid4 + 4];
            afh[mt][3] = ahw[(m + 8) * 12 + tid4 + 4];
            afl[mt][0] = alw[m * 12 + tid4];
            afl[mt][1] = alw[(m + 8) * 12 + tid4];
            afl[mt][2] = alw[m * 12 + tid4 + 4];
            afl[mt][3] = alw[(m + 8) * 12 + tid4 + 4];
        }
        unsigned bfh[8][2], bfl[8][2];
#pragma unroll
        for (int nt = 0; nt < 8; nt++) {
            int nn = wn + nt * 8 + gid;
            bfh[nt][0] = bhw[nn * 12 + tid4];
            bfh[nt][1] = bhw[nn * 12 + tid4 + 4];
            bfl[nt][0] = blw[nn * 12 + tid4];
            bfl[nt][1] = blw[nn * 12 + tid4 + 4];
        }
#pragma unroll
        for (int mt = 0; mt < 2; mt++)
#pragma unroll
            for (int nt = 0; nt < 8; nt++)
                mma_bf16(c[mt][nt], afh[mt], bfh[nt][0], bfh[nt][1]);
#pragma unroll
        for (int mt = 0; mt < 2; mt++)
#pragma unroll
            for (int nt = 0; nt < 8; nt++)
                mma_bf16(c[mt][nt], afh[mt], bfl[nt][0], bfl[nt][1]);
#pragma unroll
        for (int mt = 0; mt < 2; mt++)
#pragma unroll
            for (int nt = 0; nt < 8; nt++)
                mma_bf16(c[mt][nt], afl[mt], bfh[nt][0], bfh[nt][1]);
        if (more) {
            int nxt = cur ^ 1;
            fill(Ah + nxt * 3072 + lr * 24 + lc, Al + nxt * 3072 + lr * 24 + lc, ga0, ga1);
            fill(Bh + nxt * 3072 + lr * 24 + lc, Bl + nxt * 3072 + lr * 24 + lc, gb0, gb1);
            __syncthreads();
            cur = nxt;
        }
    }

#pragma unroll
    for (int mt = 0; mt < 2; mt++) {
        int row = bm + wm + mt * 16 + gid;
#pragma unroll
        for (int nt = 0; nt < 8; nt++) {
            int col = bn + wn + nt * 8 + tid4 * 2;
            float bv0 = bias1[col], bv1 = bias1[col + 1];
            if (bias2) { bv0 += bias2[col]; bv1 += bias2[col + 1]; }
            float r0 = c[mt][nt][0] + bv0;
            float r1 = c[mt][nt][1] + bv1;
            float r2 = c[mt][nt][2] + bv0;
            float r3 = c[mt][nt][3] + bv1;
            if (RELU) {
                r0 = fmaxf(r0, 0.f); r1 = fmaxf(r1, 0.f);
                r2 = fmaxf(r2, 0.f); r3 = fmaxf(r3, 0.f);
            }
            *(float2*)&C[(size_t)row * N + col]       = make_float2(r0, r1);
            *(float2*)&C[(size_t)(row + 8) * N + col] = make_float2(r2, r3);
        }
    }
}

// ======================================================================
// persistent LSTM: 128 CTAs x 2 hidden units.  This round:
//  - gate dot-product split into 4 independent accumulator chains
//  - h fill vectorized (float4 loads, 8 iters)
//  - done-masks cached in smem (m_s), reused by update phase
// ======================================================================
#define NBLK 128
#define LSTM_SMEM ((2048 + 8224 + 64 + 576 + 32) * 4)
__device__ __forceinline__ float sigmoidf(float x) { return 1.f / (1.f + expf(-x)); }

__global__ void __launch_bounds__(256)
lstm_kernel(const float* __restrict__ done,
            const float* __restrict__ h0,
            const float* __restrict__ c0,
            const float* __restrict__ whh,
            float* __restrict__ out) {
    extern __shared__ float sm[];
    float* w_s = sm;             // [k=256][r=8]
    float* h_s = sm + 2048;      // [32][257]
    float* c_s = h_s + 8224;     // [64]
    float* p_s = c_s + 64;       // [2][32][9]
    float* m_s = p_s + 576;      // [32]
    int t = threadIdx.x, blk = blockIdx.x;
    int j0 = blk * 2;

    for (int i = t; i < 2048; i += 256) {
        int k = i >> 3, r = i & 7;
        int q = r >> 1, jj = r & 1;
        w_s[i] = whh[(size_t)(q * HID + j0 + jj) * HID + k];
    }
    if (t < 64) {
        int b = t >> 1, jj = t & 1;
        c_s[t] = c0[b * HID + j0 + jj];
    }
    __syncthreads();

    int u = t & 127, half = t >> 7;
    int gb = u & 31, rq = u >> 5;
    unsigned target = 0;

    for (int step = 0; step < TT; step++) {
        float2 acc0;
        if (half == 0)
            acc0 = *(const float2*)&g_gx[(size_t)(step * BB + gb) * 4 * HID + rq * HID + j0];
        else
            acc0 = make_float2(0.f, 0.f);

        if (t < 32) m_s[t] = 1.0f - __ldg(&done[step * BB + t]);

        // h fill: float4 loads, 8 iterations; scalar stores keep 257-stride
        const float* hsrc = (step == 0) ? h0 : g_h;
        for (int i = t; i < BB * HID / 4; i += 256) {
            int b = i >> 6;                     // 64 float4 per batch row
            int k = (i & 63) * 4;
            float4 v = *(const float4*)&hsrc[b * HID + k];
            float m = 1.0f - __ldg(&done[step * BB + b]);
            float* hp = &h_s[b * 257 + k];
            hp[0] = v.x * m; hp[1] = v.y * m;
            hp[2] = v.z * m; hp[3] = v.w * m;
        }
        __syncthreads();

        // gate dot: 4 independent accumulator chains (k = 4i + j)
        {
            const float* hp = &h_s[gb * 257 + half * 128];
            const float* wp = &w_s[(half * 128) * 8 + rq * 2];
            u64t a0 = pk2(acc0.x, acc0.y);
            u64t a1 = pk2(0.f, 0.f), a2 = a1, a3 = a1;
#pragma unroll
            for (int i = 0; i < 32; i++) {
                int k = i * 4;
                float h0v = hp[k],     h1v = hp[k + 1];
                float h2v = hp[k + 2], h3v = hp[k + 3];
                fma2(a0, pk2(h0v, h0v), *(const u64t*)&wp[(k    ) * 8]);
                fma2(a1, pk2(h1v, h1v), *(const u64t*)&wp[(k + 1) * 8]);
                fma2(a2, pk2(h2v, h2v), *(const u64t*)&wp[(k + 2) * 8]);
                fma2(a3, pk2(h3v, h3v), *(const u64t*)&wp[(k + 3) * 8]);
            }
            float2 r0 = upk2(a0), r1 = upk2(a1), r2 = upk2(a2), r3 = upk2(a3);
            float rx = (r0.x + r1.x) + (r2.x + r3.x);
            float ry = (r0.y + r1.y) + (r2.y + r3.y);
            float* pp = &p_s[half * 288 + gb * 9 + rq * 2];
            pp[0] = rx; pp[1] = ry;
        }
        __syncthreads();

        if (t < 64) {
            int b = t >> 1, jj = t & 1;
            float m = m_s[b];
            const float* p0 = &p_s[b * 9];
            const float* p1 = &p_s[288 + b * 9];
            float gi = p0[0 + jj] + p1[0 + jj];
            float gf = p0[2 + jj] + p1[2 + jj];
            float gg = p0[4 + jj] + p1[4 + jj];
            float go = p0[6 + jj] + p1[6 + jj];
            float I = sigmoidf(gi);
            float F = sigmoidf(gf);
            float G = tanhf(gg);
            float O = sigmoidf(go);
            float c_new = F * (m * c_s[t]) + I * G;
            c_s[t] = c_new;
            float h_new = O * tanhf(c_new);
            g_h[b * HID + j0 + jj] = h_new;
            g_hs[(size_t)(step * BB + b) * HID + j0 + jj] = h_new;
            if (step == TT - 1) {
                out[OUT_H + b * HID + j0 + jj] = h_new;
                out[OUT_C + b * HID + j0 + jj] = c_new;
            }
        }
        __threadfence();
        __syncthreads();
        if (t == 0) {
            atomicAdd(&g_bar, 1u);
            target += NBLK;
            while (*(volatile unsigned*)&g_bar < target) { }
        }
        __syncthreads();
    }

    if (t == 0) {
        unsigned v = atomicAdd(&g_exit, 1u);
        if (v == NBLK - 1) {
            atomicExch(&g_exit, 0u);
            atomicExch(&g_bar, 0u);
            __threadfence();
        }
    }
}

// ======================================================================
// heads
// ======================================================================
__global__ void heads_kernel(const float* __restrict__ pw,
                             const float* __restrict__ pb,
                             const float* __restrict__ vw,
                             const float* __restrict__ vb,
                             float* __restrict__ out) {
    __shared__ float ws[7 * 256];
    int t = threadIdx.x;
    for (int i = t; i < 6 * 256; i += 256) ws[i] = pw[i];
    if (t < 256) ws[1536 + t] = vw[t];
    __syncthreads();

    int warp = t >> 5, lane = t & 31;
    int row = blockIdx.x * 8 + warp;
    const float* hrow = g_hs + (size_t)row * 256;
    float p[7];
#pragma unroll
    for (int a = 0; a < 7; a++) p[a] = 0.f;
    for (int k = lane; k < 256; k += 32) {
        float hv = hrow[k];
#pragma unroll
        for (int a = 0; a < 7; a++) p[a] += hv * ws[a * 256 + k];
    }
#pragma unroll
    for (int a = 0; a < 7; a++)
#pragma unroll
        for (int off = 16; off; off >>= 1)
            p[a] += __shfl_xor_sync(0xffffffffu, p[a], off);
    if (lane == 0) {
#pragma unroll
        for (int a = 0; a < 6; a++) out[(size_t)row * 6 + a] = p[a] + pb[a];
        out[OUT_V + row] = p[6] + vb[0];
    }
}

// ======================================================================
// launch
// ======================================================================
extern "C" void kernel_launch(void* const* d_in, const int* in_sizes, int n_in,
                              void* d_out, int out_size) {
    const float* image = (const float*)d_in[0];
    const float* done  = (const float*)d_in[1];
    const float* h0    = (const float*)d_in[2];
    const float* c0    = (const float*)d_in[3];
    const float* c1w   = (const float*)d_in[4];
    const float* c1b   = (const float*)d_in[5];
    const float* c2w   = (const float*)d_in[6];
    const float* c2b   = (const float*)d_in[7];
    const float* c3w   = (const float*)d_in[8];
    const float* c3b   = (const float*)d_in[9];
    const float* fcw   = (const float*)d_in[10];
    const float* fcb   = (const float*)d_in[11];
    const float* wih   = (const float*)d_in[12];
    const float* whh   = (const float*)d_in[13];
    const float* bih   = (const float*)d_in[14];
    const float* bhh   = (const float*)d_in[15];
    const float* polw  = (const float*)d_in[16];
    const float* polb  = (const float*)d_in[17];
    const float* valw  = (const float*)d_in[18];
    const float* valb  = (const float*)d_in[19];
    float* out = (float*)d_out;

    auto conv1 = conv_bf3_kernel<3, 8, 4, 84, 20, 32, 192, 4, 13, true>;
    auto conv2 = conv_bf3_kernel<32, 4, 2, 20, 9,  64, 128, 2, 6,  false>;

    cudaFuncSetAttribute(conv1, cudaFuncAttributeMaxDynamicSharedMemorySize, C1B_SMEM);
    cudaFuncSetAttribute(conv2, cudaFuncAttributeMaxDynamicSharedMemorySize, C2B_SMEM);
    cudaFuncSetAttribute(conv3_mma_kernel, cudaFuncAttributeMaxDynamicSharedMemorySize, C3M_SMEM);
    cudaFuncSetAttribute(gemm_bf3_kernel<true>,  cudaFuncAttributeMaxDynamicSharedMemorySize, GEMM_SMEM);
    cudaFuncSetAttribute(gemm_bf3_kernel<false>, cudaFuncAttributeMaxDynamicSharedMemorySize, GEMM_SMEM);
    cudaFuncSetAttribute(lstm_kernel, cudaFuncAttributeMaxDynamicSharedMemorySize, LSTM_SMEM);

    void *p_c1, *p_c2, *p_c3, *p_feat, *p_gx;
    cudaGetSymbolAddress(&p_c1, g_c1);
    cudaGetSymbolAddress(&p_c2, g_c2);
    cudaGetSymbolAddress(&p_c3, g_c3);
    cudaGetSymbolAddress(&p_feat, g_feat);
    cudaGetSymbolAddress(&p_gx, g_gx);

    conv1<<<NTB, 256, C1B_SMEM>>>(image, c1w, c1b, (float*)p_c1);
    conv2<<<NTB, 256, C2B_SMEM>>>((const float*)p_c1, c2w, c2b, (float*)p_c2);
    conv3_mma_kernel<<<NTB, 256, C3M_SMEM>>>((const float*)p_c2, c3w, c3b, (float*)p_c3);

    // feats = relu(flat @ fc_w^T + fc_b)   [4096,512]  (bf16x3 ~= fp32)
    gemm_bf3_kernel<true><<<dim3(FEAT / 128, NTB / 128), 256, GEMM_SMEM>>>(
        (const float*)p_c3, fcw, fcb, nullptr, (float*)p_feat, NTB, FEAT, FLAT);

    // gates_x = feats @ w_ih^T + b_ih + b_hh   [4096,1024]  (bf16x3 ~= fp32)
    gemm_bf3_kernel<false><<<dim3((4 * HID) / 128, NTB / 128), 256, GEMM_SMEM>>>(
        (const float*)p_feat, wih, bih, bhh, (float*)p_gx, NTB, 4 * HID, FEAT);

    lstm_kernel<<<NBLK, 256, LSTM_SMEM>>>(done, h0, c0, whh, out);

    heads_kernel<<<NTB / 8, 256>>>(polw, polb, valw, valb, out);
}

// round 17
// speedup vs baseline: 1.2320x; 1.0569x over previous
#include <cuda_runtime.h>
#include <cuda_bf16.h>
#include <math.h>

// ---------------- problem constants ----------------
#define TT   128
#define BB   32
#define NTB  4096            // T*B
#define HID  256
#define FEAT 512
#define FLAT 3136            // 64*7*7
#define NACT 6

// output layout: logits[4096*6], v[4096], h[32*256], c[32*256]
#define OUT_V    24576
#define OUT_H    28672
#define OUT_C    36864

// ---------------- packed f32x2 helpers (LSTM) ----------------
typedef unsigned long long u64t;
__device__ __forceinline__ u64t pk2(float lo, float hi) {
    u64t r;
    asm("mov.b64 %0, {%1, %2};" : "=l"(r) : "f"(lo), "f"(hi));
    return r;
}
__device__ __forceinline__ void fma2(u64t& d, u64t a, u64t b) {
    asm("fma.rn.f32x2 %0, %1, %2, %0;" : "+l"(d) : "l"(a), "l"(b));
}
__device__ __forceinline__ float2 upk2(u64t v) {
    float2 f;
    asm("mov.b64 {%0, %1}, %2;" : "=f"(f.x), "=f"(f.y) : "l"(v));
    return f;
}

// ---------------- bf16 helpers ----------------
__device__ __forceinline__ void mma_bf16(float c[4], const unsigned a[4],
                                         unsigned b0, unsigned b1) {
    asm volatile(
        "mma.sync.aligned.m16n8k16.row.col.f32.bf16.bf16.f32 "
        "{%0,%1,%2,%3}, {%4,%5,%6,%7}, {%8,%9}, {%0,%1,%2,%3};"
        : "+f"(c[0]), "+f"(c[1]), "+f"(c[2]), "+f"(c[3])
        : "r"(a[0]), "r"(a[1]), "r"(a[2]), "r"(a[3]), "r"(b0), "r"(b1));
}
__device__ __forceinline__ void bf_split(float x, __nv_bfloat16& h, __nv_bfloat16& l) {
    h = __float2bfloat16(x);
    l = __float2bfloat16(x - __bfloat162float(h));
}
__device__ __forceinline__ unsigned pack_bf2(__nv_bfloat16 a, __nv_bfloat16 b) {
    __nv_bfloat162 v(a, b);
    return *(unsigned*)&v;
}
__device__ __forceinline__ unsigned lo32(u64t v) { return (unsigned)v; }
__device__ __forceinline__ unsigned hi32(u64t v) { return (unsigned)(v >> 32); }

// ---------------- scratch ----------------
__device__ float g_c1[(size_t)NTB*32*20*20];
__device__ float g_c2[(size_t)NTB*64*9*9];
__device__ float g_c3[(size_t)NTB*64*7*7];
__device__ float g_feat[(size_t)NTB*FEAT];
__device__ float g_gx[(size_t)NTB*4*HID];
__device__ float g_hs[(size_t)NTB*HID];
__device__ float g_h[BB*HID];
__device__ unsigned g_bar;
__device__ unsigned g_exit;

// ======================================================================
// conv1 SPLIT: 2 CTAs per image (oy halves), 3 CTAs/SM.
// Each CTA: 44 input rows (40*hy .. 40*hy+43), 200 output positions.
// K=192 single weight chunk. bf16x3, clamped gathers.
// ======================================================================
#define C1_IPAIR 5544                      // 3 * 44 * 84 / 2
#define C1_SMEM (((C1_IPAIR + 8) * 2 + 32 * 194) * 4 + 192 * 4)
__global__ void __launch_bounds__(256, 3)
conv1_split_kernel(const float* __restrict__ src,
                   const float* __restrict__ w,
                   const float* __restrict__ bias) {
    constexpr int K = 192, MCH = 32, WSW = 194;
    constexpr int NTT = 25, NG = 4, MAXNT = 7;   // 200 pos / 8

    extern __shared__ unsigned smw[];
    unsigned* iw = smw;                          // (C1_IPAIR+8)*2
    unsigned* ww = iw + (C1_IPAIR + 8) * 2;      // 32*194
    int* kof = (int*)(ww + MCH * WSW);           // [192]

    int bx = blockIdx.x, t = threadIdx.x;
    int n = bx >> 1, hy = bx & 1;

    // input: channels of 44 rows starting at global row 40*hy
    const float2* s2 = (const float2*)(src + (size_t)n * 21168);
    for (int i = t; i < C1_IPAIR; i += 256) {
        int c = i / 1848, rp = i % 1848;         // 1848 pairs per 44-row channel
        float2 x = s2[c * 3528 + hy * 1680 + rp];
        float x0 = x.x * (1.0f / 255.0f);
        float x1 = x.y * (1.0f / 255.0f);
        __nv_bfloat16 h0, l0, h1, l1;
        bf_split(x0, h0, l0);
        bf_split(x1, h1, l1);
        iw[2 * i]     = pack_bf2(h0, h1);
        iw[2 * i + 1] = pack_bf2(l0, l1);
    }
    if (t < 16) iw[C1_IPAIR * 2 + t] = 0u;
    for (int i = t; i < K; i += 256) {
        int c = i >> 6, r = i & 63;
        int ky = r >> 3, kx = r & 7;
        kof[i] = c * 3696 + ky * 84 + kx;        // local 44-row channel stride
    }
    // weights: [co][c][ky][kx] row-major == [m][K] in kof order
    for (int i = t; i < MCH * (K / 2); i += 256) {
        int m = i / (K / 2), q = i % (K / 2);
        float x0 = w[(size_t)m * K + 2 * q];
        float x1 = w[(size_t)m * K + 2 * q + 1];
        __nv_bfloat16 h0, l0, h1, l1;
        bf_split(x0, h0, l0);
        bf_split(x1, h1, l1);
        ww[m * WSW + 2 * q]     = pack_bf2(h0, h1);
        ww[m * WSW + 2 * q + 1] = pack_bf2(l0, l1);
    }
    __syncthreads();

    int wid = t >> 5, lane = t & 31;
    int gid = lane >> 2, tid4 = lane & 3;
    int wm = wid >> 2, ng = wid & 3;             // 2 m-tiles x 4 n-groups
    int m0 = wm * 16 + gid;

    int nbase[MAXNT];
#pragma unroll
    for (int j = 0; j < MAXNT; j++) {
        int nt = ng + j * NG;
        int p = nt * 8 + gid;
        if (p >= 200) p = 199;                   // clamp
        int oy = p / 20, ox = p % 20;
        nbase[j] = oy * 336 + ox * 4;            // 4*84 = 336
    }

    float acc[MAXNT][4];
#pragma unroll
    for (int j = 0; j < MAXNT; j++)
        acc[j][0] = acc[j][1] = acc[j][2] = acc[j][3] = 0.f;

    for (int k16 = 0; k16 < K / 16; k16++) {
        int wq = k16 * 8 + tid4;
        u64t A0 = *(const u64t*)&ww[m0 * WSW + 2 * wq];
        u64t A1 = *(const u64t*)&ww[(m0 + 8) * WSW + 2 * wq];
        u64t A2 = *(const u64t*)&ww[m0 * WSW + 2 * wq + 8];
        u64t A3 = *(const u64t*)&ww[(m0 + 8) * WSW + 2 * wq + 8];
        unsigned ah[4] = {lo32(A0), lo32(A1), lo32(A2), lo32(A3)};
        unsigned al[4] = {hi32(A0), hi32(A1), hi32(A2), hi32(A3)};

        int oa = kof[k16 * 16 + 2 * tid4];
        int ob = kof[k16 * 16 + 8 + 2 * tid4];
#pragma unroll
        for (int j = 0; j < MAXNT; j += 2) {
            u64t P0 = *(const u64t*)&iw[(oa + nbase[j])];
            u64t P1 = *(const u64t*)&iw[(ob + nbase[j])];
            u64t Q0 = 0, Q1 = 0;
            if (j + 1 < MAXNT) {
                Q0 = *(const u64t*)&iw[(oa + nbase[j + 1])];
                Q1 = *(const u64t*)&iw[(ob + nbase[j + 1])];
            }
            mma_bf16(acc[j], ah, lo32(P0), lo32(P1));
            if (j + 1 < MAXNT) mma_bf16(acc[j + 1], ah, lo32(Q0), lo32(Q1));
            mma_bf16(acc[j], ah, hi32(P0), hi32(P1));
            if (j + 1 < MAXNT) mma_bf16(acc[j + 1], ah, hi32(Q0), hi32(Q1));
            mma_bf16(acc[j], al, lo32(P0), lo32(P1));
            if (j + 1 < MAXNT) mma_bf16(acc[j + 1], al, lo32(Q0), lo32(Q1));
        }
    }

    float* base = g_c1 + (size_t)n * 12800 + hy * 200;
    float b0 = __ldg(&bias[m0]);
    float b1 = __ldg(&bias[m0 + 8]);
#pragma unroll
    for (int j = 0; j < MAXNT; j++) {
        int nt = ng + j * NG;
        if (nt >= NTT) continue;
        int col = nt * 8 + tid4 * 2;             // < 200, col+1 < 200
        base[(size_t)m0 * 400 + col]           = fmaxf(acc[j][0] + b0, 0.f);
        base[(size_t)m0 * 400 + col + 1]       = fmaxf(acc[j][1] + b0, 0.f);
        base[(size_t)(m0 + 8) * 400 + col]     = fmaxf(acc[j][2] + b1, 0.f);
        base[(size_t)(m0 + 8) * 400 + col + 1] = fmaxf(acc[j][3] + b1, 0.f);
    }
}

// ======================================================================
// conv2 bf16x3 (round-15 champion, unchanged).
// ======================================================================
template<int CIN,int KW,int S,int IW,int OW,int MCH,int KC,int NG,int MAXNT,bool SCALE>
__global__ void __launch_bounds__(256, 2)
conv_bf3_kernel(const float* __restrict__ src,
                const float* __restrict__ w,
                const float* __restrict__ bias,
                float* __restrict__ dst) {
    constexpr int K    = CIN * KW * KW;
    constexpr int NPOS = OW * OW;
    constexpr int ISZ  = CIN * IW * IW;
    constexpr int NCH  = K / KC;
    constexpr int WSW  = KC + 2;
    constexpr int NTT  = (NPOS + 7) / 8;
    constexpr int IPAIR = ISZ / 2;

    extern __shared__ unsigned smw[];
    unsigned* iw = smw;
    unsigned* ww = iw + (IPAIR + 8) * 2;
    int* kof = (int*)(ww + MCH * WSW);

    int n = blockIdx.x, t = threadIdx.x;

    const float* s = src + (size_t)n * ISZ;
    for (int i = t; i < IPAIR; i += 256) {
        float x0 = s[2 * i], x1 = s[2 * i + 1];
        if (SCALE) { x0 *= (1.0f / 255.0f); x1 *= (1.0f / 255.0f); }
        __nv_bfloat16 h0, l0, h1, l1;
        bf_split(x0, h0, l0);
        bf_split(x1, h1, l1);
        iw[2 * i]     = pack_bf2(h0, h1);
        iw[2 * i + 1] = pack_bf2(l0, l1);
    }
    if (t < 16) iw[IPAIR * 2 + t] = 0u;
    for (int i = t; i < K; i += 256) {
        int c = i / (KW * KW), r = i % (KW * KW);
        kof[i] = (c * IW + r / KW) * IW + (r % KW);
    }

    int wid = t >> 5, lane = t & 31;
    int gid = lane >> 2, tid4 = lane & 3;
    int wm, ng;
    if (MCH == 32) { wm = wid >> 2; ng = wid & 3; }
    else           { wm = wid >> 1; ng = wid & 1; }
    int m0 = wm * 16 + gid;

    int nbase[MAXNT];
#pragma unroll
    for (int j = 0; j < MAXNT; j++) {
        int nt = ng + j * NG;
        int p = nt * 8 + gid;
        if (p >= NPOS) p = NPOS - 1;
        int oy = p / OW, ox = p % OW;
        nbase[j] = oy * S * IW + ox * S;
    }

    float acc[MAXNT][4];
#pragma unroll
    for (int j = 0; j < MAXNT; j++)
        acc[j][0] = acc[j][1] = acc[j][2] = acc[j][3] = 0.f;

    for (int ck = 0; ck < NCH; ck++) {
        __syncthreads();
        for (int i = t; i < MCH * (KC / 2); i += 256) {
            int m = i / (KC / 2), q = i % (KC / 2);
            float x0 = w[(size_t)m * K + ck * KC + 2 * q];
            float x1 = w[(size_t)m * K + ck * KC + 2 * q + 1];
            __nv_bfloat16 h0, l0, h1, l1;
            bf_split(x0, h0, l0);
            bf_split(x1, h1, l1);
            ww[m * WSW + 2 * q]     = pack_bf2(h0, h1);
            ww[m * WSW + 2 * q + 1] = pack_bf2(l0, l1);
        }
        __syncthreads();

        for (int k16 = 0; k16 < KC / 16; k16++) {
            int wq = k16 * 8 + tid4;
            u64t A0 = *(const u64t*)&ww[m0 * WSW + 2 * wq];
            u64t A1 = *(const u64t*)&ww[(m0 + 8) * WSW + 2 * wq];
            u64t A2 = *(const u64t*)&ww[m0 * WSW + 2 * wq + 8];
            u64t A3 = *(const u64t*)&ww[(m0 + 8) * WSW + 2 * wq + 8];
            unsigned ah[4] = {lo32(A0), lo32(A1), lo32(A2), lo32(A3)};
            unsigned al[4] = {hi32(A0), hi32(A1), hi32(A2), hi32(A3)};

            int kbase = ck * KC + k16 * 16;
            int oa = kof[kbase + 2 * tid4];
            int ob = kof[kbase + 8 + 2 * tid4];
#pragma unroll
            for (int j = 0; j < MAXNT; j += 2) {
                u64t P0 = *(const u64t*)&iw[(oa + nbase[j])];
                u64t P1 = *(const u64t*)&iw[(ob + nbase[j])];
                u64t Q0 = 0, Q1 = 0;
                if (j + 1 < MAXNT) {
                    Q0 = *(const u64t*)&iw[(oa + nbase[j + 1])];
                    Q1 = *(const u64t*)&iw[(ob + nbase[j + 1])];
                }
                mma_bf16(acc[j], ah, lo32(P0), lo32(P1));
                if (j + 1 < MAXNT) mma_bf16(acc[j + 1], ah, lo32(Q0), lo32(Q1));
                mma_bf16(acc[j], ah, hi32(P0), hi32(P1));
                if (j + 1 < MAXNT) mma_bf16(acc[j + 1], ah, hi32(Q0), hi32(Q1));
                mma_bf16(acc[j], al, lo32(P0), lo32(P1));
                if (j + 1 < MAXNT) mma_bf16(acc[j + 1], al, lo32(Q0), lo32(Q1));
            }
        }
    }

    float* base = dst + (size_t)n * MCH * NPOS;
    float b0 = __ldg(&bias[m0]);
    float b1 = __ldg(&bias[m0 + 8]);
#pragma unroll
    for (int j = 0; j < MAXNT; j++) {
        int nt = ng + j * NG;
        if (nt >= NTT) continue;
        int col = nt * 8 + tid4 * 2;
        if (col < NPOS) {
            base[(size_t)m0 * NPOS + col]       = fmaxf(acc[j][0] + b0, 0.f);
            base[(size_t)(m0 + 8) * NPOS + col] = fmaxf(acc[j][2] + b1, 0.f);
        }
        if (col + 1 < NPOS) {
            base[(size_t)m0 * NPOS + col + 1]       = fmaxf(acc[j][1] + b0, 0.f);
            base[(size_t)(m0 + 8) * NPOS + col + 1] = fmaxf(acc[j][3] + b1, 0.f);
        }
    }
}

#define C2B_SMEM (((12800/2 + 8) * 2 + 64 * 130) * 4 + 512 * 4)

// ======================================================================
// conv3 bf16x3 MMA: KC 192 -> 96 (smem 136KB -> 109KB => 2 CTAs/SM).
// Chunk-sequential k order: numerics identical.
// ======================================================================
#define C3M_ISZ   5184
#define C3M_IPAIR 2592
#define C3M_IWRDS ((C3M_IPAIR + 8) * 2)
#define C3M_KC    96
#define C3M_WSW   98
#define C3M_SMEM  ((2 * C3M_IWRDS + 64 * C3M_WSW) * 4 + 768 * 4)
__global__ void __launch_bounds__(256, 2)
conv3_mma_kernel(const float* __restrict__ src,
                 const float* __restrict__ w,
                 const float* __restrict__ bias,
                 float* __restrict__ dst) {
    constexpr int IW = 9, OW = 7, NPOS = 49, MCH = 64;
    constexpr int K = 768, KC = C3M_KC, NCH = K / KC;   // 8 chunks
    constexpr int NTT = 7, NG = 2, MAXNT = 4;

    extern __shared__ unsigned smw[];
    unsigned* iw = smw;
    unsigned* jw = iw + C3M_IWRDS;
    unsigned* ww = jw + C3M_IWRDS;
    int* kof = (int*)(ww + 64 * C3M_WSW);

    int n = blockIdx.x, t = threadIdx.x;
    const float* s = src + (size_t)n * C3M_ISZ;

    for (int u = t; u < C3M_IPAIR + 8; u += 256) {
        float x0 = (2*u   < C3M_ISZ) ? s[2*u]   : 0.f;
        float x1 = (2*u+1 < C3M_ISZ) ? s[2*u+1] : 0.f;
        float x2 = (2*u+2 < C3M_ISZ) ? s[2*u+2] : 0.f;
        __nv_bfloat16 h0,l0,h1,l1,h2,l2;
        bf_split(x0,h0,l0); bf_split(x1,h1,l1); bf_split(x2,h2,l2);
        iw[2*u]   = pack_bf2(h0,h1); iw[2*u+1] = pack_bf2(l0,l1);
        jw[2*u]   = pack_bf2(h1,h2); jw[2*u+1] = pack_bf2(l1,l2);
    }
    for (int i = t; i < K; i += 256) {
        int kx = i & 3, ky = (i >> 2) % 3, c = i / 12;
        kof[i] = c * 81 + ky * 9 + kx;
    }

    int wid = t >> 5, lane = t & 31;
    int gid = lane >> 2, tid4 = lane & 3;
    int wm = wid >> 1, ng = wid & 1;
    int m0 = wm * 16 + gid;

    int nbase[MAXNT];
#pragma unroll
    for (int j = 0; j < MAXNT; j++) {
        int nt = ng + j * NG;
        int p = nt * 8 + gid;
        if (p >= NPOS) p = NPOS - 1;
        int oy = p / OW, ox = p % OW;
        nbase[j] = oy * IW + ox;
    }

    float acc[MAXNT][4];
#pragma unroll
    for (int j = 0; j < MAXNT; j++)
        acc[j][0] = acc[j][1] = acc[j][2] = acc[j][3] = 0.f;

    for (int ck = 0; ck < NCH; ck++) {
        __syncthreads();
        for (int i = t; i < MCH * (KC / 2); i += 256) {
            int m = i / (KC / 2), q = i % (KC / 2);
            int k = ck * KC + 2 * q;
            int kx = k & 3, ky = (k >> 2) % 3, c = k / 12;
            float x0 = w[((size_t)(m * 64 + c) * 3 + ky) * 3 + kx];
            float x1 = (kx == 0) ? w[((size_t)(m * 64 + c) * 3 + ky) * 3 + 1] : 0.f;
            __nv_bfloat16 h0, l0, h1, l1;
            bf_split(x0, h0, l0);
            bf_split(x1, h1, l1);
            ww[m * C3M_WSW + 2 * q]     = pack_bf2(h0, h1);
            ww[m * C3M_WSW + 2 * q + 1] = pack_bf2(l0, l1);
        }
        __syncthreads();

        for (int k16 = 0; k16 < KC / 16; k16++) {
            int wq = k16 * 8 + tid4;
            u64t A0 = *(const u64t*)&ww[m0 * C3M_WSW + 2 * wq];
            u64t A1 = *(const u64t*)&ww[(m0 + 8) * C3M_WSW + 2 * wq];
            u64t A2 = *(const u64t*)&ww[m0 * C3M_WSW + 2 * wq + 8];
            u64t A3 = *(const u64t*)&ww[(m0 + 8) * C3M_WSW + 2 * wq + 8];
            unsigned ah[4] = {lo32(A0), lo32(A1), lo32(A2), lo32(A3)};
            unsigned al[4] = {hi32(A0), hi32(A1), hi32(A2), hi32(A3)};

            int kbase = ck * KC + k16 * 16;
            int oa = kof[kbase + 2 * tid4];
            int ob = kof[kbase + 8 + 2 * tid4];
#pragma unroll
            for (int j = 0; j < MAXNT; j += 2) {
                int e0 = oa + nbase[j];
                int e1 = ob + nbase[j];
                const unsigned* pp0 = (e0 & 1) ? (jw + e0 - 1) : (iw + e0);
                const unsigned* pp1 = (e1 & 1) ? (jw + e1 - 1) : (iw + e1);
                u64t P0 = *(const u64t*)pp0;
                u64t P1 = *(const u64t*)pp1;
                int f0 = oa + nbase[j + 1];
                int f1 = ob + nbase[j + 1];
                const unsigned* qq0 = (f0 & 1) ? (jw + f0 - 1) : (iw + f0);
                const unsigned* qq1 = (f1 & 1) ? (jw + f1 - 1) : (iw + f1);
                u64t Q0 = *(const u64t*)qq0;
                u64t Q1 = *(const u64t*)qq1;
                mma_bf16(acc[j],     ah, lo32(P0), lo32(P1));
                mma_bf16(acc[j + 1], ah, lo32(Q0), lo32(Q1));
                mma_bf16(acc[j],     ah, hi32(P0), hi32(P1));
                mma_bf16(acc[j + 1], ah, hi32(Q0), hi32(Q1));
                mma_bf16(acc[j],     al, lo32(P0), lo32(P1));
                mma_bf16(acc[j + 1], al, lo32(Q0), lo32(Q1));
            }
        }
    }

    float* base = dst + (size_t)n * MCH * NPOS;
    float b0 = __ldg(&bias[m0]);
    float b1 = __ldg(&bias[m0 + 8]);
#pragma unroll
    for (int j = 0; j < MAXNT; j++) {
        int nt = ng + j * NG;
        if (nt >= NTT) continue;
        int col = nt * 8 + tid4 * 2;
        if (col < NPOS) {
            base[(size_t)m0 * NPOS + col]       = fmaxf(acc[j][0] + b0, 0.f);
            base[(size_t)(m0 + 8) * NPOS + col] = fmaxf(acc[j][2] + b1, 0.f);
        }
        if (col + 1 < NPOS) {
            base[(size_t)m0 * NPOS + col + 1]       = fmaxf(acc[j][1] + b0, 0.f);
            base[(size_t)(m0 + 8) * NPOS + col + 1] = fmaxf(acc[j][3] + b1, 0.f);
        }
    }
}

// ======================================================================
// bf16x3 GEMM (champion, unchanged).
// ======================================================================
#define GEMM_SMEM 49152
template <bool RELU>
__global__ void __launch_bounds__(256)
gemm_bf3_kernel(const float* __restrict__ A,
                const float* __restrict__ Bw,
                const float* __restrict__ bias1,
                const float* __restrict__ bias2,
                float* __restrict__ C,
                int M, int N, int K) {
    extern __shared__ __nv_bfloat16 gsm[];
    __nv_bfloat16* Ah = gsm;
    __nv_bfloat16* Al = gsm + 6144;
    __nv_bfloat16* Bh = gsm + 12288;
    __nv_bfloat16* Bl = gsm + 18432;

    int bm = blockIdx.y * 128, bn = blockIdx.x * 128;
    int t = threadIdx.x;
    int wid = t >> 5, lane = t & 31;
    int gid = lane >> 2, tid4 = lane & 3;
    int wm = (wid >> 1) * 32;
    int wn = (wid & 1) * 64;
    int lr = t >> 1, lc = (t & 1) * 8;

    float c[2][8][4];
#pragma unroll
    for (int mt = 0; mt < 2; mt++)
#pragma unroll
        for (int nt = 0; nt < 8; nt++)
#pragma unroll
            for (int q = 0; q < 4; q++) c[mt][nt][q] = 0.f;

    const float* Ap = A + (size_t)(bm + lr) * K + lc;
    const float* Bp = Bw + (size_t)(bn + lr) * K + lc;

    auto fill = [&](__nv_bfloat16* dh, __nv_bfloat16* dl,
                    float4 f0, float4 f1) {
        float v[8] = {f0.x, f0.y, f0.z, f0.w, f1.x, f1.y, f1.z, f1.w};
        unsigned hw[4], lw[4];
#pragma unroll
        for (int i = 0; i < 4; i++) {
            __nv_bfloat16 h0, l0, h1, l1;
            bf_split(v[2*i], h0, l0);
            bf_split(v[2*i+1], h1, l1);
            hw[i] = pack_bf2(h0, h1);
            lw[i] = pack_bf2(l0, l1);
        }
        *(uint4*)dh = make_uint4(hw[0], hw[1], hw[2], hw[3]);
        *(uint4*)dl = make_uint4(lw[0], lw[1], lw[2], lw[3]);
    };

    {
        float4 a0 = *(const float4*)(Ap);
        float4 a1 = *(const float4*)(Ap + 4);
        float4 b0 = *(const float4*)(Bp);
        float4 b1 = *(const float4*)(Bp + 4);
        fill(Ah + lr * 24 + lc, Al + lr * 24 + lc, a0, a1);
        fill(Bh + lr * 24 + lc, Bl + lr * 24 + lc, b0, b1);
    }
    __syncthreads();

    int cur = 0;
    for (int k0 = 0; k0 < K; k0 += 16) {
        bool more = (k0 + 16) < K;
        float4 ga0, ga1, gb0, gb1;
        if (more) {
            ga0 = *(const float4*)(Ap + k0 + 16);
            ga1 = *(const float4*)(Ap + k0 + 20);
            gb0 = *(const float4*)(Bp + k0 + 16);
            gb1 = *(const float4*)(Bp + k0 + 20);
        }
        const unsigned* ahw = (const unsigned*)(Ah + cur * 3072);
        const unsigned* alw = (const unsigned*)(Al + cur * 3072);
        const unsigned* bhw = (const unsigned*)(Bh + cur * 3072);
        const unsigned* blw = (const unsigned*)(Bl + cur * 3072);
        unsigned afh[2][4], afl[2][4];
#pragma unroll
        for (int mt = 0; mt < 2; mt++) {
            int m = wm + mt * 16 + gid;
            afh[mt][0] = ahw[m * 12 + tid4];
            afh[mt][1] = ahw[(m + 8) * 12 + tid4];
            afh[mt][2] = ahw[m * 12 + tid4 + 4];
            afh[mt][3] = ahw[(m + 8) * 12 + tid4 + 4];
            afl[mt][0] = alw[m * 12 + tid4];
            afl[mt][1] = alw[(m + 8) * 12 + tid4];
            afl[mt][2] = alw[m * 12 + tid4 + 4];
            afl[mt][3] = alw[(m + 8) * 12 + tid4 + 4];
        }
        unsigned bfh[8][2], bfl[8][2];
#pragma unroll
        for (int nt = 0; nt < 8; nt++) {
            int nn = wn + nt * 8 + gid;
            bfh[nt][0] = bhw[nn * 12 + tid4];
            bfh[nt][1] = bhw[nn * 12 + tid4 + 4];
            bfl[nt][0] = blw[nn * 12 + tid4];
            bfl[nt][1] = blw[nn * 12 + tid4 + 4];
        }
#pragma unroll
        for (int mt = 0; mt < 2; mt++)
#pragma unroll
            for (int nt = 0; nt < 8; nt++)
                mma_bf16(c[mt][nt], afh[mt], bfh[nt][0], bfh[nt][1]);
#pragma unroll
        for (int mt = 0; mt < 2; mt++)
#pragma unroll
            for (int nt = 0; nt < 8; nt++)
                mma_bf16(c[mt][nt], afh[mt], bfl[nt][0], bfl[nt][1]);
#pragma unroll
        for (int mt = 0; mt < 2; mt++)
#pragma unroll
            for (int nt = 0; nt < 8; nt++)
                mma_bf16(c[mt][nt], afl[mt], bfh[nt][0], bfh[nt][1]);
        if (more) {
            int nxt = cur ^ 1;
            fill(Ah + nxt * 3072 + lr * 24 + lc, Al + nxt * 3072 + lr * 24 + lc, ga0, ga1);
            fill(Bh + nxt * 3072 + lr * 24 + lc, Bl + nxt * 3072 + lr * 24 + lc, gb0, gb1);
            __syncthreads();
            cur = nxt;
        }
    }

#pragma unroll
    for (int mt = 0; mt < 2; mt++) {
        int row = bm + wm + mt * 16 + gid;
#pragma unroll
        for (int nt = 0; nt < 8; nt++) {
            int col = bn + wn + nt * 8 + tid4 * 2;
            float bv0 = bias1[col], bv1 = bias1[col + 1];
            if (bias2) { bv0 += bias2[col]; bv1 += bias2[col + 1]; }
            float r0 = c[mt][nt][0] + bv0;
            float r1 = c[mt][nt][1] + bv1;
            float r2 = c[mt][nt][2] + bv0;
            float r3 = c[mt][nt][3] + bv1;
            if (RELU) {
                r0 = fmaxf(r0, 0.f); r1 = fmaxf(r1, 0.f);
                r2 = fmaxf(r2, 0.f); r3 = fmaxf(r3, 0.f);
            }
            *(float2*)&C[(size_t)row * N + col]       = make_float2(r0, r1);
            *(float2*)&C[(size_t)(row + 8) * N + col] = make_float2(r2, r3);
        }
    }
}

// ======================================================================
// persistent LSTM (round-16 champion, unchanged).
// ======================================================================
#define NBLK 128
#define LSTM_SMEM ((2048 + 8224 + 64 + 576 + 32) * 4)
__device__ __forceinline__ float sigmoidf(float x) { return 1.f / (1.f + expf(-x)); }

__global__ void __launch_bounds__(256)
lstm_kernel(const float* __restrict__ done,
            const float* __restrict__ h0,
            const float* __restrict__ c0,
            const float* __restrict__ whh,
            float* __restrict__ out) {
    extern __shared__ float sm[];
    float* w_s = sm;
    float* h_s = sm + 2048;
    float* c_s = h_s + 8224;
    float* p_s = c_s + 64;
    float* m_s = p_s + 576;
    int t = threadIdx.x, blk = blockIdx.x;
    int j0 = blk * 2;

    for (int i = t; i < 2048; i += 256) {
        int k = i >> 3, r = i & 7;
        int q = r >> 1, jj = r & 1;
        w_s[i] = whh[(size_t)(q * HID + j0 + jj) * HID + k];
    }
    if (t < 64) {
        int b = t >> 1, jj = t & 1;
        c_s[t] = c0[b * HID + j0 + jj];
    }
    __syncthreads();

    int u = t & 127, half = t >> 7;
    int gb = u & 31, rq = u >> 5;
    unsigned target = 0;

    for (int step = 0; step < TT; step++) {
        float2 acc0;
        if (half == 0)
            acc0 = *(const float2*)&g_gx[(size_t)(step * BB + gb) * 4 * HID + rq * HID + j0];
        else
            acc0 = make_float2(0.f, 0.f);

        if (t < 32) m_s[t] = 1.0f - __ldg(&done[step * BB + t]);

        const float* hsrc = (step == 0) ? h0 : g_h;
        for (int i = t; i < BB * HID / 4; i += 256) {
            int b = i >> 6;
            int k = (i & 63) * 4;
            float4 v = *(const float4*)&hsrc[b * HID + k];
            float m = 1.0f - __ldg(&done[step * BB + b]);
            float* hp = &h_s[b * 257 + k];
            hp[0] = v.x * m; hp[1] = v.y * m;
            hp[2] = v.z * m; hp[3] = v.w * m;
        }
        __syncthreads();

        {
            const float* hp = &h_s[gb * 257 + half * 128];
            const float* wp = &w_s[(half * 128) * 8 + rq * 2];
            u64t a0 = pk2(acc0.x, acc0.y);
            u64t a1 = pk2(0.f, 0.f), a2 = a1, a3 = a1;
#pragma unroll
            for (int i = 0; i < 32; i++) {
                int k = i * 4;
                float h0v = hp[k],     h1v = hp[k + 1];
                float h2v = hp[k + 2], h3v = hp[k + 3];
                fma2(a0, pk2(h0v, h0v), *(const u64t*)&wp[(k    ) * 8]);
                fma2(a1, pk2(h1v, h1v), *(const u64t*)&wp[(k + 1) * 8]);
                fma2(a2, pk2(h2v, h2v), *(const u64t*)&wp[(k + 2) * 8]);
                fma2(a3, pk2(h3v, h3v), *(const u64t*)&wp[(k + 3) * 8]);
            }
            float2 r0 = upk2(a0), r1 = upk2(a1), r2 = upk2(a2), r3 = upk2(a3);
            float rx = (r0.x + r1.x) + (r2.x + r3.x);
            float ry = (r0.y + r1.y) + (r2.y + r3.y);
            float* pp = &p_s[half * 288 + gb * 9 + rq * 2];
            pp[0] = rx; pp[1] = ry;
        }
        __syncthreads();

        if (t < 64) {
            int b = t >> 1, jj = t & 1;
            float m = m_s[b];
            const float* p0 = &p_s[b * 9];
            const float* p1 = &p_s[288 + b * 9];
            float gi = p0[0 + jj] + p1[0 + jj];
            float gf = p0[2 + jj] + p1[2 + jj];
            float gg = p0[4 + jj] + p1[4 + jj];
            float go = p0[6 + jj] + p1[6 + jj];
            float I = sigmoidf(gi);
            float F = sigmoidf(gf);
            float G = tanhf(gg);
            float O = sigmoidf(go);
            float c_new = F * (m * c_s[t]) + I * G;
            c_s[t] = c_new;
            float h_new = O * tanhf(c_new);
            g_h[b * HID + j0 + jj] = h_new;
            g_hs[(size_t)(step * BB + b) * HID + j0 + jj] = h_new;
            if (step == TT - 1) {
                out[OUT_H + b * HID + j0 + jj] = h_new;
                out[OUT_C + b * HID + j0 + jj] = c_new;
            }
        }
        __threadfence();
        __syncthreads();
        if (t == 0) {
            atomicAdd(&g_bar, 1u);
            target += NBLK;
            while (*(volatile unsigned*)&g_bar < target) { }
        }
        __syncthreads();
    }

    if (t == 0) {
        unsigned v = atomicAdd(&g_exit, 1u);
        if (v == NBLK - 1) {
            atomicExch(&g_exit, 0u);
            atomicExch(&g_bar, 0u);
            __threadfence();
        }
    }
}

// ======================================================================
// heads
// ======================================================================
__global__ void heads_kernel(const float* __restrict__ pw,
                             const float* __restrict__ pb,
                             const float* __restrict__ vw,
                             const float* __restrict__ vb,
                             float* __restrict__ out) {
    __shared__ float ws[7 * 256];
    int t = threadIdx.x;
    for (int i = t; i < 6 * 256; i += 256) ws[i] = pw[i];
    if (t < 256) ws[1536 + t] = vw[t];
    __syncthreads();

    int warp = t >> 5, lane = t & 31;
    int row = blockIdx.x * 8 + warp;
    const float* hrow = g_hs + (size_t)row * 256;
    float p[7];
#pragma unroll
    for (int a = 0; a < 7; a++) p[a] = 0.f;
    for (int k = lane; k < 256; k += 32) {
        float hv = hrow[k];
#pragma unroll
        for (int a = 0; a < 7; a++) p[a] += hv * ws[a * 256 + k];
    }
#pragma unroll
    for (int a = 0; a < 7; a++)
#pragma unroll
        for (int off = 16; off; off >>= 1)
            p[a] += __shfl_xor_sync(0xffffffffu, p[a], off);
    if (lane == 0) {
#pragma unroll
        for (int a = 0; a < 6; a++) out[(size_t)row * 6 + a] = p[a] + pb[a];
        out[OUT_V + row] = p[6] + vb[0];
    }
}

// ======================================================================
// launch
// ======================================================================
extern "C" void kernel_launch(void* const* d_in, const int* in_sizes, int n_in,
                              void* d_out, int out_size) {
    const float* image = (const float*)d_in[0];
    const float* done  = (const float*)d_in[1];
    const float* h0    = (const float*)d_in[2];
    const float* c0    = (const float*)d_in[3];
    const float* c1w   = (const float*)d_in[4];
    const float* c1b   = (const float*)d_in[5];
    const float* c2w   = (const float*)d_in[6];
    const float* c2b   = (const float*)d_in[7];
    const float* c3w   = (const float*)d_in[8];
    const float* c3b   = (const float*)d_in[9];
    const float* fcw   = (const float*)d_in[10];
    const float* fcb   = (const float*)d_in[11];
    const float* wih   = (const float*)d_in[12];
    const float* whh   = (const float*)d_in[13];
    const float* bih   = (const float*)d_in[14];
    const float* bhh   = (const float*)d_in[15];
    const float* polw  = (const float*)d_in[16];
    const float* polb  = (const float*)d_in[17];
    const float* valw  = (const float*)d_in[18];
    const float* valb  = (const float*)d_in[19];
    float* out = (float*)d_out;

    auto conv2 = conv_bf3_kernel<32, 4, 2, 20, 9, 64, 128, 2, 6, false>;

    cudaFuncSetAttribute(conv1_split_kernel, cudaFuncAttributeMaxDynamicSharedMemorySize, C1_SMEM);
    cudaFuncSetAttribute(conv2, cudaFuncAttributeMaxDynamicSharedMemorySize, C2B_SMEM);
    cudaFuncSetAttribute(conv3_mma_kernel, cudaFuncAttributeMaxDynamicSharedMemorySize, C3M_SMEM);
    cudaFuncSetAttribute(gemm_bf3_kernel<true>,  cudaFuncAttributeMaxDynamicSharedMemorySize, GEMM_SMEM);
    cudaFuncSetAttribute(gemm_bf3_kernel<false>, cudaFuncAttributeMaxDynamicSharedMemorySize, GEMM_SMEM);
    cudaFuncSetAttribute(lstm_kernel, cudaFuncAttributeMaxDynamicSharedMemorySize, LSTM_SMEM);

    void *p_c1, *p_c2, *p_c3, *p_feat, *p_gx;
    cudaGetSymbolAddress(&p_c1, g_c1);
    cudaGetSymbolAddress(&p_c2, g_c2);
    cudaGetSymbolAddress(&p_c3, g_c3);
    cudaGetSymbolAddress(&p_feat, g_feat);
    cudaGetSymbolAddress(&p_gx, g_gx);

    conv1_split_kernel<<<2 * NTB, 256, C1_SMEM>>>(image, c1w, c1b);
    conv2<<<NTB, 256, C2B_SMEM>>>((const float*)p_c1, c2w, c2b, (float*)p_c2);
    conv3_mma_kernel<<<NTB, 256, C3M_SMEM>>>((const float*)p_c2, c3w, c3b, (float*)p_c3);

    // feats = relu(flat @ fc_w^T + fc_b)   [4096,512]  (bf16x3 ~= fp32)
    gemm_bf3_kernel<true><<<dim3(FEAT / 128, NTB / 128), 256, GEMM_SMEM>>>(
        (const float*)p_c3, fcw, fcb, nullptr, (float*)p_feat, NTB, FEAT, FLAT);

    // gates_x = feats @ w_ih^T + b_ih + b_hh   [4096,1024]  (bf16x3 ~= fp32)
    gemm_bf3_kernel<false><<<dim3((4 * HID) / 128, NTB / 128), 256, GEMM_SMEM>>>(
        (const float*)p_feat, wih, bih, bhh, (float*)p_gx, NTB, 4 * HID, FEAT);

    lstm_kernel<<<NBLK, 256, LSTM_SMEM>>>(done, h0, c0, whh, out);

    heads_kernel<<<NTB / 8, 256>>>(polw, polb, valw, valb, out);
}